// round 13
// baseline (speedup 1.0000x reference)
#include <cuda_runtime.h>
#include <cstdint>
#include <cstdio>

#define D 128
#define MAXN 50000
#define LDA 132   // padded lead dim (floats) for tf32 mma fragment loads
#define LDT 68    // padded lead dim (bf16x2 words) for edge t tile

// Scratch (device globals: allocation-free contract). 16B-aligned for vector ld/st.
__device__ __align__(16) float g_PQR[(size_t)MAXN * 384];  // [N][384]: P=h@W1a^T, Q=h@W1b^T, R=h@U1a^T
__device__ __align__(16) float g_agg[(size_t)MAXN * D];    // scatter-add target
__device__ __align__(16) uint4 g_W2pack[8 * 4 * 2 * 32];   // [ks8][wcc][nfpair][lane] bf16 B-frags (coalesced)
__device__ int g_oddor;                                     // OR of odd 32-bit words of edge buffer

__device__ __forceinline__ unsigned f2tf(float x){
    unsigned u; asm("cvt.rna.tf32.f32 %0, %1;" : "=r"(u) : "f"(x)); return u;
}
__device__ __forceinline__ unsigned f2bf2(float lo, float hi){
    unsigned u; asm("cvt.rn.bf16x2.f32 %0, %1, %2;" : "=r"(u) : "f"(hi), "f"(lo)); return u;
}
__device__ __forceinline__ float silu(float x){           // exact-ish (2 MUFU)
    return x * (1.0f / (1.0f + __expf(-x)));
}
__device__ __forceinline__ float silu_fast(float x){      // 1 MUFU via hw tanh
    float hx = 0.5f * x;
    float t; asm("tanh.approx.f32 %0, %1;" : "=f"(t) : "f"(hx));
    return hx + hx * t;                                   // 0.5x(1+tanh(x/2))
}
__device__ __forceinline__ void mma8(float* c, const unsigned* a, const unsigned* b){
    asm volatile(
      "mma.sync.aligned.m16n8k8.row.col.f32.tf32.tf32.f32 "
      "{%0,%1,%2,%3},{%4,%5,%6,%7},{%8,%9},{%0,%1,%2,%3};\n"
      : "+f"(c[0]), "+f"(c[1]), "+f"(c[2]), "+f"(c[3])
      : "r"(a[0]), "r"(a[1]), "r"(a[2]), "r"(a[3]), "r"(b[0]), "r"(b[1]));
}
__device__ __forceinline__ void mma16(float* c, const unsigned* a, const unsigned* b){
    asm volatile(
      "mma.sync.aligned.m16n8k16.row.col.f32.bf16.bf16.f32 "
      "{%0,%1,%2,%3},{%4,%5,%6,%7},{%8,%9},{%0,%1,%2,%3};\n"
      : "+f"(c[0]), "+f"(c[1]), "+f"(c[2]), "+f"(c[3])
      : "r"(a[0]), "r"(a[1]), "r"(a[2]), "r"(a[3]), "r"(b[0]), "r"(b[1]));
}
__device__ __forceinline__ void red4(float* addr, float x, float y, float z, float w){
    asm volatile("red.global.add.v4.f32 [%0], {%1,%2,%3,%4};"
                 :: "l"(addr), "f"(x), "f"(y), "f"(z), "f"(w) : "memory");
}

// ---------------------------------------------------------------------------
// Probe: detect edge_index element width (int64 hi-words all zero vs int32).
// ---------------------------------------------------------------------------
__global__ void probe_kernel(const int* __restrict__ ebuf)
{
    int v = 0;
    for (int i = threadIdx.x; i < 4096; i += blockDim.x)
        v |= ebuf[2 * i + 1];
    if (v) atomicOr(&g_oddor, v);
}

// ---------------------------------------------------------------------------
// Pack W2 into warp-coalesced bf16 B-fragment entries for m16n8k16 (R12 layout).
// ---------------------------------------------------------------------------
__global__ void pack_kernel(const float* __restrict__ W2)
{
    int idx = blockIdx.x * 256 + threadIdx.x;   // word index
    if (idx >= 8 * 4 * 2 * 32 * 4) return;
    int wd   = idx & 3;
    int lane = (idx >> 2) & 31;
    int np   = (idx >> 7) & 1;
    int wcc  = (idx >> 8) & 3;
    int ks   = idx >> 10;
    int nf = np * 2 + (wd >> 1);
    int r  = wd & 1;
    int row = wcc * 32 + nf * 8 + (lane >> 2);
    int k0  = ks * 16 + (lane & 3) * 2 + r * 8;
    ((unsigned*)g_W2pack)[idx] = f2bf2(W2[row * D + k0], W2[row * D + k0 + 1]);
}

// ---------------------------------------------------------------------------
// Kernel 1: PQR = h @ Wcat^T. 512 threads, tile 32 rows x 384 cols. tf32.
// ---------------------------------------------------------------------------
__global__ __launch_bounds__(512) void gemm1_kernel(
    const float* __restrict__ h, const float* __restrict__ W1,
    const float* __restrict__ U1, int N)
{
    extern __shared__ unsigned sm[];
    unsigned* sW = sm;               // 384*LDA
    unsigned* sA = sm + 384 * LDA;   // 32*LDA
    int tid = threadIdx.x;

    for (int idx = tid; idx < 384 * D; idx += 512) {
        int r = idx >> 7, k = idx & 127;
        float v;
        if (r < 128)      v = W1[r * 257 + k];
        else if (r < 256) v = W1[(r - 128) * 257 + 128 + k];
        else              v = U1[(r - 256) * 256 + k];
        sW[r * LDA + k] = f2tf(v);
    }

    int w = tid >> 5, l = tid & 31, g = l >> 2, t4 = l & 3;
    int nbase = w * 24;
    int ntiles = (N + 31) >> 5;

    for (int tt = blockIdx.x; tt < ntiles; tt += gridDim.x) {
        __syncthreads();
        int row0 = tt << 5;
        #pragma unroll
        for (int it = 0; it < 2; ++it) {
            int idx = tid + it * 512;
            int r = idx >> 5, q = idx & 31;
            int i = row0 + r;
            float4 v = make_float4(0.f, 0.f, 0.f, 0.f);
            if (i < N) v = *(const float4*)&h[(size_t)i * D + q * 4];
            uint4 u = make_uint4(f2tf(v.x), f2tf(v.y), f2tf(v.z), f2tf(v.w));
            *(uint4*)&sA[r * LDA + q * 4] = u;
        }
        __syncthreads();

        float acc[2][3][4];
        #pragma unroll
        for (int mf = 0; mf < 2; mf++)
            #pragma unroll
            for (int nf = 0; nf < 3; nf++)
                #pragma unroll
                for (int q = 0; q < 4; q++) acc[mf][nf][q] = 0.f;

        #pragma unroll
        for (int ks = 0; ks < 16; ++ks) {
            int kb = ks * 8;
            unsigned a[2][4];
            #pragma unroll
            for (int mf = 0; mf < 2; mf++) {
                int r0 = mf * 16 + g;
                a[mf][0] = sA[r0 * LDA + kb + t4];
                a[mf][1] = sA[(r0 + 8) * LDA + kb + t4];
                a[mf][2] = sA[r0 * LDA + kb + t4 + 4];
                a[mf][3] = sA[(r0 + 8) * LDA + kb + t4 + 4];
            }
            #pragma unroll
            for (int nf = 0; nf < 3; nf++) {
                unsigned b[2];
                int n = nbase + nf * 8 + g;
                b[0] = sW[n * LDA + kb + t4];
                b[1] = sW[n * LDA + kb + t4 + 4];
                mma8(acc[0][nf], a[0], b);
                mma8(acc[1][nf], a[1], b);
            }
        }
        #pragma unroll
        for (int mf = 0; mf < 2; mf++) {
            int i0 = row0 + mf * 16 + g;
            int i1 = i0 + 8;
            #pragma unroll
            for (int nf = 0; nf < 3; nf++) {
                int col = nbase + nf * 8 + t4 * 2;
                if (i0 < N) *(float2*)&g_PQR[(size_t)i0 * 384 + col] = make_float2(acc[mf][nf][0], acc[mf][nf][1]);
                if (i1 < N) *(float2*)&g_PQR[(size_t)i1 * 384 + col] = make_float2(acc[mf][nf][2], acc[mf][nf][3]);
            }
        }
    }
}

// ---------------------------------------------------------------------------
// Edge tile builder: gather P/Q, fuse layer-1, write bf16x2 t tile.
// Each warp covers edges w, w+8, ..., w+56 of the 64-edge tile.
// ---------------------------------------------------------------------------
__device__ __forceinline__ void build_tile(
    unsigned* __restrict__ sT, const float* __restrict__ coords,
    const int* __restrict__ e32, const long long* __restrict__ e64, bool is64,
    const float* __restrict__ sb1, const float* __restrict__ swc,
    int e0, int N, int E, int w, int l)
{
    #pragma unroll
    for (int half = 0; half < 2; ++half) {
        float4 pv[4], qv[4]; float dv[4]; int el[4];
        #pragma unroll
        for (int it = 0; it < 4; ++it) {
            int e_loc = w + (half * 4 + it) * 8;
            el[it] = e_loc;
            int e = e0 + e_loc;
            int v = 0;
            if (l < 2 && e < E)
                v = is64 ? (int)e64[(size_t)l * E + e] : e32[(size_t)l * E + e];
            int s = __shfl_sync(0xffffffffu, v, 0);
            int r = __shfl_sync(0xffffffffu, v, 1);
            if ((unsigned)s >= (unsigned)N) s = 0;
            if ((unsigned)r >= (unsigned)N) r = 0;
            float cd = 0.f;
            if (l < 3) cd = coords[s * 3 + l] - coords[r * 3 + l];
            float dx = __shfl_sync(0xffffffffu, cd, 0);
            float dy = __shfl_sync(0xffffffffu, cd, 1);
            float dz = __shfl_sync(0xffffffffu, cd, 2);
            dv[it] = sqrtf(dx * dx + dy * dy + dz * dz);
            pv[it] = *(const float4*)&g_PQR[(size_t)s * 384 + l * 4];
            qv[it] = *(const float4*)&g_PQR[(size_t)r * 384 + 128 + l * 4];
        }
        #pragma unroll
        for (int it = 0; it < 4; ++it) {
            int c = l * 4;
            float x0 = pv[it].x + qv[it].x + dv[it] * swc[c + 0] + sb1[c + 0];
            float x1 = pv[it].y + qv[it].y + dv[it] * swc[c + 1] + sb1[c + 1];
            float x2 = pv[it].z + qv[it].z + dv[it] * swc[c + 2] + sb1[c + 2];
            float x3 = pv[it].w + qv[it].w + dv[it] * swc[c + 3] + sb1[c + 3];
            uint2 st = make_uint2(f2bf2(silu_fast(x0), silu_fast(x1)),
                                  f2bf2(silu_fast(x2), silu_fast(x3)));
            *(uint2*)&sT[el[it] * LDT + l * 2] = st;
        }
    }
}

// ---------------------------------------------------------------------------
// Kernel 2: edge kernel v8 = R12 + double-buffered sT software pipeline.
// Tile = 64 edges, 256 threads, 3 CTAs/SM. ONE sync per tile:
//   mma(cur) -> build(next) -> scatter -> sync
// ---------------------------------------------------------------------------
__global__ __launch_bounds__(256, 3) void edge_kernel(
    const float* __restrict__ coords, const void* __restrict__ eraw,
    const float* __restrict__ W1, const float* __restrict__ b1,
    const float* __restrict__ b2, int N, int E)
{
    extern __shared__ unsigned sm[];
    // two t-tile buffers
    float* sb1 = (float*)(sm + 2 * 64 * LDT);
    float* sb2 = sb1 + 128;
    float* swc = sb2 + 128;
    int tid = threadIdx.x;

    const bool is64 = (g_oddor == 0);
    const int*       e32 = (const int*)eraw;
    const long long* e64 = (const long long*)eraw;

    if (tid < 128) { sb1[tid] = b1[tid]; sb2[tid] = b2[tid]; swc[tid] = W1[tid * 257 + 256]; }
    __syncthreads();

    int w = tid >> 5, l = tid & 31, g = l >> 2, t4 = l & 3;
    int wr = w & 1, wcc = w >> 1;     // 2 row-groups (32 rows) x 4 col-groups (32 cols)
    int ntiles = (E + 63) >> 6;

    int tt = blockIdx.x;
    if (tt >= ntiles) return;

    int cur = 0;
    build_tile(sm, coords, e32, e64, is64, sb1, swc, tt << 6, N, E, w, l);
    __syncthreads();

    while (true) {
        int e0 = tt << 6;
        unsigned* sT = sm + cur * 64 * LDT;

        // ---- GEMM2 (bf16): warp computes 32 rows (wr) x 32 cols (wcc) ----
        float acc[2][4][4];
        #pragma unroll
        for (int mf = 0; mf < 2; mf++)
            #pragma unroll
            for (int nf = 0; nf < 4; nf++)
                #pragma unroll
                for (int q = 0; q < 4; q++) acc[mf][nf][q] = 0.f;

        #pragma unroll
        for (int ks = 0; ks < 8; ++ks) {
            int kw = ks * 8;            // 8 bf16x2 words = 16 k-cols per step
            unsigned a[2][4];
            #pragma unroll
            for (int mf = 0; mf < 2; mf++) {
                int r0 = wr * 32 + mf * 16 + g;
                a[mf][0] = sT[r0 * LDT + kw + t4];
                a[mf][1] = sT[(r0 + 8) * LDT + kw + t4];
                a[mf][2] = sT[r0 * LDT + kw + t4 + 4];
                a[mf][3] = sT[(r0 + 8) * LDT + kw + t4 + 4];
            }
            uint4 q0 = g_W2pack[((ks * 4 + wcc) * 2 + 0) * 32 + l];
            uint4 q1 = g_W2pack[((ks * 4 + wcc) * 2 + 1) * 32 + l];
            unsigned bb[8] = { q0.x, q0.y, q0.z, q0.w, q1.x, q1.y, q1.z, q1.w };
            #pragma unroll
            for (int nf = 0; nf < 4; nf++) {
                mma16(acc[0][nf], a[0], &bb[nf * 2]);
                mma16(acc[1][nf], a[1], &bb[nf * 2]);
            }
        }

        // ---- prefetch/build NEXT tile into the other buffer (overlaps with
        //      other warps' mma reads of sT[cur]; gather latency hidden) ----
        int ttn = tt + gridDim.x;
        bool have_next = (ttn < ntiles);
        if (have_next)
            build_tile(sm + (cur ^ 1) * 64 * LDT, coords, e32, e64, is64,
                       sb1, swc, ttn << 6, N, E, w, l);

        // ---- scatter direct from regs: bias + silu, shfl-pair -> red.v4 ----
        int rowlane = wr * 32 + l;     // this warp's 32 tile-rows
        int vrec = 0;
        if (e0 + rowlane < E)
            vrec = is64 ? (int)e64[(size_t)E + e0 + rowlane] : e32[(size_t)E + e0 + rowlane];
        if ((unsigned)vrec >= (unsigned)N) vrec = 0;

        #pragma unroll
        for (int mf = 0; mf < 2; mf++) {
            #pragma unroll
            for (int hh = 0; hh < 2; ++hh) {
                int rsel = mf * 16 + hh * 8 + g;
                int rec = __shfl_sync(0xffffffffu, vrec, rsel);
                bool valid = (e0 + wr * 32 + rsel) < E;
                #pragma unroll
                for (int nf = 0; nf < 4; nf++) {
                    int col = wcc * 32 + nf * 8 + t4 * 2;
                    float m0 = silu_fast(acc[mf][nf][hh * 2]     + sb2[col]);
                    float m1 = silu_fast(acc[mf][nf][hh * 2 + 1] + sb2[col + 1]);
                    // lane t4^1 holds the adjacent column pair
                    float n0 = __shfl_xor_sync(0xffffffffu, m0, 1);
                    float n1 = __shfl_xor_sync(0xffffffffu, m1, 1);
                    if (((t4 & 1) == 0) && valid) {
                        int cb = wcc * 32 + nf * 8 + (t4 >> 1) * 4;  // t4=0 -> +0, t4=2 -> +4
                        red4(&g_agg[(size_t)rec * D + cb], m0, m1, n0, n1);
                    }
                }
            }
        }

        if (!have_next) break;
        __syncthreads();   // next buffer fully built; cur buffer reads all done
        cur ^= 1;
        tt = ttn;
    }
}

// ---------------------------------------------------------------------------
// Kernel 3: node update. 512 threads, tile 128 nodes. tf32 + exact silu.
// ---------------------------------------------------------------------------
__global__ __launch_bounds__(512) void node_kernel(
    const float* __restrict__ h, const float* __restrict__ U1,
    const float* __restrict__ U2, const float* __restrict__ c1,
    const float* __restrict__ c2, float* __restrict__ out, int N)
{
    extern __shared__ unsigned sm[];
    unsigned* sW = sm;               // 256*LDA (U1b rows 0..127, U2 rows 128..255)
    unsigned* sA = sm + 256 * LDA;   // 128*LDA (agg tile, then t tile)
    float* sc1 = (float*)(sA + 128 * LDA);
    float* sc2 = sc1 + 128;
    int tid = threadIdx.x;

    #pragma unroll
    for (int it = 0; it < 16; ++it) {
        int idx = tid + it * 512;
        int r = idx >> 5, q = idx & 31;
        float4 v;
        if (r < 128) v = *(const float4*)&U1[r * 256 + 128 + q * 4];
        else         v = *(const float4*)&U2[(r - 128) * D + q * 4];
        uint4 u = make_uint4(f2tf(v.x), f2tf(v.y), f2tf(v.z), f2tf(v.w));
        *(uint4*)&sW[r * LDA + q * 4] = u;
    }
    if (tid < 128) { sc1[tid] = c1[tid]; sc2[tid] = c2[tid]; }

    int w = tid >> 5, l = tid & 31, g = l >> 2, t4 = l & 3;
    int wr = w >> 1, wc = w & 1;
    int ntiles = (N + 127) >> 7;

    for (int tt = blockIdx.x; tt < ntiles; tt += gridDim.x) {
        __syncthreads();
        int n0 = tt << 7;
        #pragma unroll
        for (int it = 0; it < 8; ++it) {
            int idx = tid + it * 512;
            int r = idx >> 5, q = idx & 31;
            int i = n0 + r;
            float4 v = make_float4(0.f, 0.f, 0.f, 0.f);
            if (i < N) v = *(const float4*)&g_agg[(size_t)i * D + q * 4];
            uint4 u = make_uint4(f2tf(v.x), f2tf(v.y), f2tf(v.z), f2tf(v.w));
            *(uint4*)&sA[r * LDA + q * 4] = u;
        }
        __syncthreads();

        float acc[8][4];
        #pragma unroll
        for (int nf = 0; nf < 8; nf++)
            #pragma unroll
            for (int q = 0; q < 4; q++) acc[nf][q] = 0.f;

        #pragma unroll
        for (int ks = 0; ks < 16; ++ks) {
            int kb = ks * 8;
            unsigned a[4];
            int r0 = wr * 16 + g;
            a[0] = sA[r0 * LDA + kb + t4];
            a[1] = sA[(r0 + 8) * LDA + kb + t4];
            a[2] = sA[r0 * LDA + kb + t4 + 4];
            a[3] = sA[(r0 + 8) * LDA + kb + t4 + 4];
            #pragma unroll
            for (int nf = 0; nf < 8; nf++) {
                unsigned b[2];
                int n = wc * 64 + nf * 8 + g;
                b[0] = sW[n * LDA + kb + t4];
                b[1] = sW[n * LDA + kb + t4 + 4];
                mma8(acc[nf], a, b);
            }
        }
        __syncthreads();  // all warps done reading agg tile before overwrite with t

        int rA = wr * 16 + g;
        int i0 = n0 + rA, i1 = i0 + 8;
        #pragma unroll
        for (int nf = 0; nf < 8; nf++) {
            int col = wc * 64 + nf * 8 + t4 * 2;
            float r00 = 0.f, r01 = 0.f, r10 = 0.f, r11 = 0.f;
            if (i0 < N) { float2 rv = *(const float2*)&g_PQR[(size_t)i0 * 384 + 256 + col]; r00 = rv.x; r01 = rv.y; }
            if (i1 < N) { float2 rv = *(const float2*)&g_PQR[(size_t)i1 * 384 + 256 + col]; r10 = rv.x; r11 = rv.y; }
            sA[rA * LDA + col]           = f2tf(silu(acc[nf][0] + r00 + sc1[col]));
            sA[rA * LDA + col + 1]       = f2tf(silu(acc[nf][1] + r01 + sc1[col + 1]));
            sA[(rA + 8) * LDA + col]     = f2tf(silu(acc[nf][2] + r10 + sc1[col]));
            sA[(rA + 8) * LDA + col + 1] = f2tf(silu(acc[nf][3] + r11 + sc1[col + 1]));
        }
        __syncthreads();

        float acc2[8][4];
        #pragma unroll
        for (int nf = 0; nf < 8; nf++)
            #pragma unroll
            for (int q = 0; q < 4; q++) acc2[nf][q] = 0.f;

        #pragma unroll
        for (int ks = 0; ks < 16; ++ks) {
            int kb = ks * 8;
            unsigned a[4];
            int r0 = wr * 16 + g;
            a[0] = sA[r0 * LDA + kb + t4];
            a[1] = sA[(r0 + 8) * LDA + kb + t4];
            a[2] = sA[r0 * LDA + kb + t4 + 4];
            a[3] = sA[(r0 + 8) * LDA + kb + t4 + 4];
            #pragma unroll
            for (int nf = 0; nf < 8; nf++) {
                unsigned b[2];
                int n = 128 + wc * 64 + nf * 8 + g;
                b[0] = sW[n * LDA + kb + t4];
                b[1] = sW[n * LDA + kb + t4 + 4];
                mma8(acc2[nf], a, b);
            }
        }

        #pragma unroll
        for (int nf = 0; nf < 8; nf++) {
            int col = wc * 64 + nf * 8 + t4 * 2;
            if (i0 < N) {
                float2 hv = *(const float2*)&h[(size_t)i0 * D + col];
                *(float2*)&out[(size_t)i0 * D + col] =
                    make_float2(hv.x + acc2[nf][0] + sc2[col], hv.y + acc2[nf][1] + sc2[col + 1]);
            }
            if (i1 < N) {
                float2 hv = *(const float2*)&h[(size_t)i1 * D + col];
                *(float2*)&out[(size_t)i1 * D + col] =
                    make_float2(hv.x + acc2[nf][2] + sc2[col], hv.y + acc2[nf][3] + sc2[col + 1]);
            }
        }
    }
}

// ---------------------------------------------------------------------------
extern "C" void kernel_launch(void* const* d_in, const int* in_sizes, int n_in,
                              void* d_out, int out_size)
{
    const float* h      = (const float*)d_in[0];
    const float* coords = (const float*)d_in[1];
    const void*  eraw   = (const void*)d_in[2];
    const float* W1     = (const float*)d_in[3];
    const float* b1     = (const float*)d_in[4];
    const float* W2     = (const float*)d_in[5];
    const float* b2     = (const float*)d_in[6];
    const float* U1     = (const float*)d_in[7];
    const float* c1     = (const float*)d_in[8];
    const float* U2     = (const float*)d_in[9];
    const float* c2     = (const float*)d_in[10];

    int N = in_sizes[0] / D;
    int E = in_sizes[2] / 2;
    if (N > MAXN) N = MAXN;

    const int SMEM1 = (384 * LDA + 32 * LDA) * 4;                // 219,648
    const int SMEM2 = 2 * 64 * LDT * 4 + 3 * 128 * 4;            // 36,352
    const int SMEM3 = (256 * LDA + 128 * LDA) * 4 + 2 * 128 * 4; // 203,776

    cudaFuncSetAttribute(gemm1_kernel, cudaFuncAttributeMaxDynamicSharedMemorySize, SMEM1);
    cudaFuncSetAttribute(edge_kernel,  cudaFuncAttributeMaxDynamicSharedMemorySize, SMEM2);
    cudaFuncSetAttribute(node_kernel,  cudaFuncAttributeMaxDynamicSharedMemorySize, SMEM3);

    void* aggPtr = nullptr;
    cudaGetSymbolAddress(&aggPtr, g_agg);
    cudaMemsetAsync(aggPtr, 0, (size_t)N * D * sizeof(float));
    void* flagPtr = nullptr;
    cudaGetSymbolAddress(&flagPtr, g_oddor);
    cudaMemsetAsync(flagPtr, 0, sizeof(int));

    probe_kernel<<<1, 256>>>((const int*)eraw);
    pack_kernel<<<32, 256>>>(W2);
    gemm1_kernel<<<152, 512, SMEM1>>>(h, W1, U1, N);
    edge_kernel<<<444, 256, SMEM2>>>(coords, eraw, W1, b1, b2, N, E);
    node_kernel<<<152, 512, SMEM3>>>(h, U1, U2, c1, c2, (float*)d_out, N);
}

// round 14
// speedup vs baseline: 1.0322x; 1.0322x over previous
#include <cuda_runtime.h>
#include <cstdint>
#include <cstdio>

#define D 128
#define MAXN 50000
#define LDA 132   // padded lead dim (floats) for tf32 mma fragment loads
#define LDT 68    // padded lead dim (bf16x2 words) for edge t tile

// Scratch (device globals: allocation-free contract). 16B-aligned for vector ld/st.
__device__ __align__(16) float g_PQR[(size_t)MAXN * 384];  // [N][384]: P=h@W1a^T, Q=h@W1b^T, R=h@U1a^T
__device__ __align__(16) float g_agg[(size_t)MAXN * D];    // scatter-add target
__device__ __align__(16) uint4 g_W2pack[8 * 4 * 2 * 32];   // bf16 B-frags for edge GEMM2 (coalesced)
__device__ __align__(16) uint4 g_Upack[2 * 16 * 2 * 4 * 32]; // tf32 B-frags for node GEMMs (131KB)
__device__ int g_oddor;                                     // OR of odd 32-bit words of edge buffer

__device__ __forceinline__ unsigned f2tf(float x){
    unsigned u; asm("cvt.rna.tf32.f32 %0, %1;" : "=r"(u) : "f"(x)); return u;
}
__device__ __forceinline__ unsigned f2bf2(float lo, float hi){
    unsigned u; asm("cvt.rn.bf16x2.f32 %0, %1, %2;" : "=r"(u) : "f"(hi), "f"(lo)); return u;
}
__device__ __forceinline__ float silu(float x){           // exact-ish (2 MUFU)
    return x * (1.0f / (1.0f + __expf(-x)));
}
__device__ __forceinline__ float silu_fast(float x){      // 1 MUFU via hw tanh
    float hx = 0.5f * x;
    float t; asm("tanh.approx.f32 %0, %1;" : "=f"(t) : "f"(hx));
    return hx + hx * t;                                   // 0.5x(1+tanh(x/2))
}
__device__ __forceinline__ void mma8(float* c, const unsigned* a, const unsigned* b){
    asm volatile(
      "mma.sync.aligned.m16n8k8.row.col.f32.tf32.tf32.f32 "
      "{%0,%1,%2,%3},{%4,%5,%6,%7},{%8,%9},{%0,%1,%2,%3};\n"
      : "+f"(c[0]), "+f"(c[1]), "+f"(c[2]), "+f"(c[3])
      : "r"(a[0]), "r"(a[1]), "r"(a[2]), "r"(a[3]), "r"(b[0]), "r"(b[1]));
}
__device__ __forceinline__ void mma16(float* c, const unsigned* a, const unsigned* b){
    asm volatile(
      "mma.sync.aligned.m16n8k16.row.col.f32.bf16.bf16.f32 "
      "{%0,%1,%2,%3},{%4,%5,%6,%7},{%8,%9},{%0,%1,%2,%3};\n"
      : "+f"(c[0]), "+f"(c[1]), "+f"(c[2]), "+f"(c[3])
      : "r"(a[0]), "r"(a[1]), "r"(a[2]), "r"(a[3]), "r"(b[0]), "r"(b[1]));
}
__device__ __forceinline__ void red4(float* addr, float x, float y, float z, float w){
    asm volatile("red.global.add.v4.f32 [%0], {%1,%2,%3,%4};"
                 :: "l"(addr), "f"(x), "f"(y), "f"(z), "f"(w) : "memory");
}

// ---------------------------------------------------------------------------
// Probe: detect edge_index element width (int64 hi-words all zero vs int32).
// ---------------------------------------------------------------------------
__global__ void probe_kernel(const int* __restrict__ ebuf)
{
    int v = 0;
    for (int i = threadIdx.x; i < 4096; i += blockDim.x)
        v |= ebuf[2 * i + 1];
    if (v) atomicOr(&g_oddor, v);
}

// ---------------------------------------------------------------------------
// Pack W2 into warp-coalesced bf16 B-fragment entries for m16n8k16 (R12 layout).
// ---------------------------------------------------------------------------
__global__ void pack_kernel(const float* __restrict__ W2)
{
    int idx = blockIdx.x * 256 + threadIdx.x;   // word index
    if (idx >= 8 * 4 * 2 * 32 * 4) return;
    int wd   = idx & 3;
    int lane = (idx >> 2) & 31;
    int np   = (idx >> 7) & 1;
    int wcc  = (idx >> 8) & 3;
    int ks   = idx >> 10;
    int nf = np * 2 + (wd >> 1);
    int r  = wd & 1;
    int row = wcc * 32 + nf * 8 + (lane >> 2);
    int k0  = ks * 16 + (lane & 3) * 2 + r * 8;
    ((unsigned*)g_W2pack)[idx] = f2bf2(W2[row * D + k0], W2[row * D + k0 + 1]);
}

// ---------------------------------------------------------------------------
// Pack U1b (L=0) and U2 (L=1) into warp-coalesced tf32 B-frag entries for mma8:
// word addr = ((((L*16+ks)*2+wc)*4+np)*32 + lane)*4 + wd
//   nf = np*2 + (wd>>1), r = wd&1
//   row = wc*64 + nf*8 + (lane>>2), col = ks*8 + (lane&3) + r*4
// ---------------------------------------------------------------------------
__global__ void pack_node_kernel(const float* __restrict__ U1,
                                 const float* __restrict__ U2)
{
    int idx = blockIdx.x * 256 + threadIdx.x;   // word index, 32768 total
    if (idx >= 2 * 16 * 2 * 4 * 32 * 4) return;
    int wd   = idx & 3;
    int lane = (idx >> 2) & 31;
    int np   = (idx >> 7) & 3;
    int wc   = (idx >> 9) & 1;
    int ks   = (idx >> 10) & 15;
    int L    = (idx >> 14) & 1;
    int nf = np * 2 + (wd >> 1);
    int r  = wd & 1;
    int row = wc * 64 + nf * 8 + (lane >> 2);
    int col = ks * 8 + (lane & 3) + r * 4;
    float v = (L == 0) ? U1[row * 256 + 128 + col] : U2[row * D + col];
    ((unsigned*)g_Upack)[idx] = f2tf(v);
}

// ---------------------------------------------------------------------------
// Kernel 1: PQR = h @ Wcat^T. 512 threads, tile 32 rows x 384 cols. tf32.
// ---------------------------------------------------------------------------
__global__ __launch_bounds__(512) void gemm1_kernel(
    const float* __restrict__ h, const float* __restrict__ W1,
    const float* __restrict__ U1, int N)
{
    extern __shared__ unsigned sm[];
    unsigned* sW = sm;               // 384*LDA
    unsigned* sA = sm + 384 * LDA;   // 32*LDA
    int tid = threadIdx.x;

    for (int idx = tid; idx < 384 * D; idx += 512) {
        int r = idx >> 7, k = idx & 127;
        float v;
        if (r < 128)      v = W1[r * 257 + k];
        else if (r < 256) v = W1[(r - 128) * 257 + 128 + k];
        else              v = U1[(r - 256) * 256 + k];
        sW[r * LDA + k] = f2tf(v);
    }

    int w = tid >> 5, l = tid & 31, g = l >> 2, t4 = l & 3;
    int nbase = w * 24;
    int ntiles = (N + 31) >> 5;

    for (int tt = blockIdx.x; tt < ntiles; tt += gridDim.x) {
        __syncthreads();
        int row0 = tt << 5;
        #pragma unroll
        for (int it = 0; it < 2; ++it) {
            int idx = tid + it * 512;
            int r = idx >> 5, q = idx & 31;
            int i = row0 + r;
            float4 v = make_float4(0.f, 0.f, 0.f, 0.f);
            if (i < N) v = *(const float4*)&h[(size_t)i * D + q * 4];
            uint4 u = make_uint4(f2tf(v.x), f2tf(v.y), f2tf(v.z), f2tf(v.w));
            *(uint4*)&sA[r * LDA + q * 4] = u;
        }
        __syncthreads();

        float acc[2][3][4];
        #pragma unroll
        for (int mf = 0; mf < 2; mf++)
            #pragma unroll
            for (int nf = 0; nf < 3; nf++)
                #pragma unroll
                for (int q = 0; q < 4; q++) acc[mf][nf][q] = 0.f;

        #pragma unroll
        for (int ks = 0; ks < 16; ++ks) {
            int kb = ks * 8;
            unsigned a[2][4];
            #pragma unroll
            for (int mf = 0; mf < 2; mf++) {
                int r0 = mf * 16 + g;
                a[mf][0] = sA[r0 * LDA + kb + t4];
                a[mf][1] = sA[(r0 + 8) * LDA + kb + t4];
                a[mf][2] = sA[r0 * LDA + kb + t4 + 4];
                a[mf][3] = sA[(r0 + 8) * LDA + kb + t4 + 4];
            }
            #pragma unroll
            for (int nf = 0; nf < 3; nf++) {
                unsigned b[2];
                int n = nbase + nf * 8 + g;
                b[0] = sW[n * LDA + kb + t4];
                b[1] = sW[n * LDA + kb + t4 + 4];
                mma8(acc[0][nf], a[0], b);
                mma8(acc[1][nf], a[1], b);
            }
        }
        #pragma unroll
        for (int mf = 0; mf < 2; mf++) {
            int i0 = row0 + mf * 16 + g;
            int i1 = i0 + 8;
            #pragma unroll
            for (int nf = 0; nf < 3; nf++) {
                int col = nbase + nf * 8 + t4 * 2;
                if (i0 < N) *(float2*)&g_PQR[(size_t)i0 * 384 + col] = make_float2(acc[mf][nf][0], acc[mf][nf][1]);
                if (i1 < N) *(float2*)&g_PQR[(size_t)i1 * 384 + col] = make_float2(acc[mf][nf][2], acc[mf][nf][3]);
            }
        }
    }
}

// ---------------------------------------------------------------------------
// Kernel 2: edge kernel (R12 structure, single sT, 2 syncs/tile, hoisted vrec).
// Tile = 64 edges, 256 threads, 3 CTAs/SM.
// ---------------------------------------------------------------------------
__global__ __launch_bounds__(256, 3) void edge_kernel(
    const float* __restrict__ coords, const void* __restrict__ eraw,
    const float* __restrict__ W1, const float* __restrict__ b1,
    const float* __restrict__ b2, int N, int E)
{
    extern __shared__ unsigned sm[];
    unsigned* sT  = sm;              // 64*LDT words (bf16x2 t tile)
    float* sb1   = (float*)(sT + 64 * LDT);
    float* sb2   = sb1 + 128;
    float* swc   = sb2 + 128;
    int tid = threadIdx.x;

    const bool is64 = (g_oddor == 0);
    const int*       e32 = (const int*)eraw;
    const long long* e64 = (const long long*)eraw;

    if (tid < 128) { sb1[tid] = b1[tid]; sb2[tid] = b2[tid]; swc[tid] = W1[tid * 257 + 256]; }
    __syncthreads();

    int w = tid >> 5, l = tid & 31, g = l >> 2, t4 = l & 3;
    int wr = w & 1, wcc = w >> 1;     // 2 row-groups (32 rows) x 4 col-groups (32 cols)
    int ntiles = (E + 63) >> 6;

    for (int tt = blockIdx.x; tt < ntiles; tt += gridDim.x) {
        int e0 = tt << 6;

        // ---- build t tile (bf16x2): each warp covers edges w, w+8, ..., w+56 ----
        #pragma unroll
        for (int half = 0; half < 2; ++half) {
            float4 pv[4], qv[4]; float dv[4]; int el[4];
            #pragma unroll
            for (int it = 0; it < 4; ++it) {
                int e_loc = w + (half * 4 + it) * 8;
                el[it] = e_loc;
                int e = e0 + e_loc;
                int v = 0;
                if (l < 2 && e < E)
                    v = is64 ? (int)e64[(size_t)l * E + e] : e32[(size_t)l * E + e];
                int s = __shfl_sync(0xffffffffu, v, 0);
                int r = __shfl_sync(0xffffffffu, v, 1);
                if ((unsigned)s >= (unsigned)N) s = 0;
                if ((unsigned)r >= (unsigned)N) r = 0;
                float cd = 0.f;
                if (l < 3) cd = coords[s * 3 + l] - coords[r * 3 + l];
                float dx = __shfl_sync(0xffffffffu, cd, 0);
                float dy = __shfl_sync(0xffffffffu, cd, 1);
                float dz = __shfl_sync(0xffffffffu, cd, 2);
                dv[it] = sqrtf(dx * dx + dy * dy + dz * dz);
                pv[it] = *(const float4*)&g_PQR[(size_t)s * 384 + l * 4];
                qv[it] = *(const float4*)&g_PQR[(size_t)r * 384 + 128 + l * 4];
            }
            #pragma unroll
            for (int it = 0; it < 4; ++it) {
                int c = l * 4;
                float x0 = pv[it].x + qv[it].x + dv[it] * swc[c + 0] + sb1[c + 0];
                float x1 = pv[it].y + qv[it].y + dv[it] * swc[c + 1] + sb1[c + 1];
                float x2 = pv[it].z + qv[it].z + dv[it] * swc[c + 2] + sb1[c + 2];
                float x3 = pv[it].w + qv[it].w + dv[it] * swc[c + 3] + sb1[c + 3];
                uint2 st = make_uint2(f2bf2(silu_fast(x0), silu_fast(x1)),
                                      f2bf2(silu_fast(x2), silu_fast(x3)));
                *(uint2*)&sT[el[it] * LDT + l * 2] = st;
            }
        }
        __syncthreads();

        // hoisted receiver-index load: latency hides under the mma loop
        int rowlane = wr * 32 + l;     // this warp's 32 tile-rows
        int vrec = 0;
        if (e0 + rowlane < E)
            vrec = is64 ? (int)e64[(size_t)E + e0 + rowlane] : e32[(size_t)E + e0 + rowlane];
        if ((unsigned)vrec >= (unsigned)N) vrec = 0;

        // ---- GEMM2 (bf16): warp computes 32 rows (wr) x 32 cols (wcc) ----
        float acc[2][4][4];
        #pragma unroll
        for (int mf = 0; mf < 2; mf++)
            #pragma unroll
            for (int nf = 0; nf < 4; nf++)
                #pragma unroll
                for (int q = 0; q < 4; q++) acc[mf][nf][q] = 0.f;

        #pragma unroll
        for (int ks = 0; ks < 8; ++ks) {
            int kw = ks * 8;            // 8 bf16x2 words = 16 k-cols per step
            unsigned a[2][4];
            #pragma unroll
            for (int mf = 0; mf < 2; mf++) {
                int r0 = wr * 32 + mf * 16 + g;
                a[mf][0] = sT[r0 * LDT + kw + t4];
                a[mf][1] = sT[(r0 + 8) * LDT + kw + t4];
                a[mf][2] = sT[r0 * LDT + kw + t4 + 4];
                a[mf][3] = sT[(r0 + 8) * LDT + kw + t4 + 4];
            }
            uint4 q0 = g_W2pack[((ks * 4 + wcc) * 2 + 0) * 32 + l];
            uint4 q1 = g_W2pack[((ks * 4 + wcc) * 2 + 1) * 32 + l];
            unsigned bb[8] = { q0.x, q0.y, q0.z, q0.w, q1.x, q1.y, q1.z, q1.w };
            #pragma unroll
            for (int nf = 0; nf < 4; nf++) {
                mma16(acc[0][nf], a[0], &bb[nf * 2]);
                mma16(acc[1][nf], a[1], &bb[nf * 2]);
            }
        }
        __syncthreads();   // sT free for next tile's t-build

        // ---- scatter direct from regs: bias + silu, shfl-pair -> red.v4 ----
        #pragma unroll
        for (int mf = 0; mf < 2; mf++) {
            #pragma unroll
            for (int hh = 0; hh < 2; ++hh) {
                int rsel = mf * 16 + hh * 8 + g;
                int rec = __shfl_sync(0xffffffffu, vrec, rsel);
                bool valid = (e0 + wr * 32 + rsel) < E;
                #pragma unroll
                for (int nf = 0; nf < 4; nf++) {
                    int col = wcc * 32 + nf * 8 + t4 * 2;
                    float m0 = silu_fast(acc[mf][nf][hh * 2]     + sb2[col]);
                    float m1 = silu_fast(acc[mf][nf][hh * 2 + 1] + sb2[col + 1]);
                    // lane t4^1 holds the adjacent column pair
                    float n0 = __shfl_xor_sync(0xffffffffu, m0, 1);
                    float n1 = __shfl_xor_sync(0xffffffffu, m1, 1);
                    if (((t4 & 1) == 0) && valid) {
                        int cb = wcc * 32 + nf * 8 + (t4 >> 1) * 4;  // t4=0 -> +0, t4=2 -> +4
                        red4(&g_agg[(size_t)rec * D + cb], m0, m1, n0, n1);
                    }
                }
            }
        }
    }
}

// ---------------------------------------------------------------------------
// Kernel 3: node update v2. 512 threads, tile 128 nodes, 2 CTAs/SM.
// Weights from L2-resident g_Upack (coalesced tf32 B-frags); smem = sA only.
// tf32 + exact silu; numerics identical to R12.
// ---------------------------------------------------------------------------
__global__ __launch_bounds__(512, 2) void node_kernel(
    const float* __restrict__ h, const float* __restrict__ c1,
    const float* __restrict__ c2, float* __restrict__ out, int N)
{
    extern __shared__ unsigned sm[];
    unsigned* sA = sm;               // 128*LDA (agg tile, then t tile)
    float* sc1 = (float*)(sA + 128 * LDA);
    float* sc2 = sc1 + 128;
    int tid = threadIdx.x;

    if (tid < 128) { sc1[tid] = c1[tid]; sc2[tid] = c2[tid]; }

    int w = tid >> 5, l = tid & 31, g = l >> 2, t4 = l & 3;
    int wr = w >> 1, wc = w & 1;
    int ntiles = (N + 127) >> 7;

    for (int tt = blockIdx.x; tt < ntiles; tt += gridDim.x) {
        __syncthreads();
        int n0 = tt << 7;
        #pragma unroll
        for (int it = 0; it < 8; ++it) {
            int idx = tid + it * 512;
            int r = idx >> 5, q = idx & 31;
            int i = n0 + r;
            float4 v = make_float4(0.f, 0.f, 0.f, 0.f);
            if (i < N) v = *(const float4*)&g_agg[(size_t)i * D + q * 4];
            uint4 u = make_uint4(f2tf(v.x), f2tf(v.y), f2tf(v.z), f2tf(v.w));
            *(uint4*)&sA[r * LDA + q * 4] = u;
        }
        __syncthreads();

        float acc[8][4];
        #pragma unroll
        for (int nf = 0; nf < 8; nf++)
            #pragma unroll
            for (int q = 0; q < 4; q++) acc[nf][q] = 0.f;

        #pragma unroll
        for (int ks = 0; ks < 16; ++ks) {
            int kb = ks * 8;
            unsigned a[4];
            int r0 = wr * 16 + g;
            a[0] = sA[r0 * LDA + kb + t4];
            a[1] = sA[(r0 + 8) * LDA + kb + t4];
            a[2] = sA[r0 * LDA + kb + t4 + 4];
            a[3] = sA[(r0 + 8) * LDA + kb + t4 + 4];
            const uint4* up = &g_Upack[(((0 * 16 + ks) * 2 + wc) * 4) * 32 + l];
            uint4 q0 = up[0], q1 = up[32], q2 = up[64], q3 = up[96];
            unsigned bb[16] = { q0.x,q0.y,q0.z,q0.w, q1.x,q1.y,q1.z,q1.w,
                                q2.x,q2.y,q2.z,q2.w, q3.x,q3.y,q3.z,q3.w };
            #pragma unroll
            for (int nf = 0; nf < 8; nf++)
                mma8(acc[nf], a, &bb[nf * 2]);
        }
        __syncthreads();  // all warps done reading agg tile before overwrite with t

        int rA = wr * 16 + g;
        int i0 = n0 + rA, i1 = i0 + 8;
        #pragma unroll
        for (int nf = 0; nf < 8; nf++) {
            int col = wc * 64 + nf * 8 + t4 * 2;
            float r00 = 0.f, r01 = 0.f, r10 = 0.f, r11 = 0.f;
            if (i0 < N) { float2 rv = *(const float2*)&g_PQR[(size_t)i0 * 384 + 256 + col]; r00 = rv.x; r01 = rv.y; }
            if (i1 < N) { float2 rv = *(const float2*)&g_PQR[(size_t)i1 * 384 + 256 + col]; r10 = rv.x; r11 = rv.y; }
            sA[rA * LDA + col]           = f2tf(silu(acc[nf][0] + r00 + sc1[col]));
            sA[rA * LDA + col + 1]       = f2tf(silu(acc[nf][1] + r01 + sc1[col + 1]));
            sA[(rA + 8) * LDA + col]     = f2tf(silu(acc[nf][2] + r10 + sc1[col]));
            sA[(rA + 8) * LDA + col + 1] = f2tf(silu(acc[nf][3] + r11 + sc1[col + 1]));
        }
        __syncthreads();

        float acc2[8][4];
        #pragma unroll
        for (int nf = 0; nf < 8; nf++)
            #pragma unroll
            for (int q = 0; q < 4; q++) acc2[nf][q] = 0.f;

        #pragma unroll
        for (int ks = 0; ks < 16; ++ks) {
            int kb = ks * 8;
            unsigned a[4];
            int r0 = wr * 16 + g;
            a[0] = sA[r0 * LDA + kb + t4];
            a[1] = sA[(r0 + 8) * LDA + kb + t4];
            a[2] = sA[r0 * LDA + kb + t4 + 4];
            a[3] = sA[(r0 + 8) * LDA + kb + t4 + 4];
            const uint4* up = &g_Upack[(((1 * 16 + ks) * 2 + wc) * 4) * 32 + l];
            uint4 q0 = up[0], q1 = up[32], q2 = up[64], q3 = up[96];
            unsigned bb[16] = { q0.x,q0.y,q0.z,q0.w, q1.x,q1.y,q1.z,q1.w,
                                q2.x,q2.y,q2.z,q2.w, q3.x,q3.y,q3.z,q3.w };
            #pragma unroll
            for (int nf = 0; nf < 8; nf++)
                mma8(acc2[nf], a, &bb[nf * 2]);
        }

        #pragma unroll
        for (int nf = 0; nf < 8; nf++) {
            int col = wc * 64 + nf * 8 + t4 * 2;
            if (i0 < N) {
                float2 hv = *(const float2*)&h[(size_t)i0 * D + col];
                *(float2*)&out[(size_t)i0 * D + col] =
                    make_float2(hv.x + acc2[nf][0] + sc2[col], hv.y + acc2[nf][1] + sc2[col + 1]);
            }
            if (i1 < N) {
                float2 hv = *(const float2*)&h[(size_t)i1 * D + col];
                *(float2*)&out[(size_t)i1 * D + col] =
                    make_float2(hv.x + acc2[nf][2] + sc2[col], hv.y + acc2[nf][3] + sc2[col + 1]);
            }
        }
    }
}

// ---------------------------------------------------------------------------
extern "C" void kernel_launch(void* const* d_in, const int* in_sizes, int n_in,
                              void* d_out, int out_size)
{
    const float* h      = (const float*)d_in[0];
    const float* coords = (const float*)d_in[1];
    const void*  eraw   = (const void*)d_in[2];
    const float* W1     = (const float*)d_in[3];
    const float* b1     = (const float*)d_in[4];
    const float* W2     = (const float*)d_in[5];
    const float* b2     = (const float*)d_in[6];
    const float* U1     = (const float*)d_in[7];
    const float* c1     = (const float*)d_in[8];
    const float* U2     = (const float*)d_in[9];
    const float* c2     = (const float*)d_in[10];

    int N = in_sizes[0] / D;
    int E = in_sizes[2] / 2;
    if (N > MAXN) N = MAXN;

    const int SMEM1 = (384 * LDA + 32 * LDA) * 4;   // 219,648
    const int SMEM2 = 64 * LDT * 4 + 3 * 128 * 4;   // 18,944
    const int SMEM3 = 128 * LDA * 4 + 2 * 128 * 4;  // 68,608

    cudaFuncSetAttribute(gemm1_kernel, cudaFuncAttributeMaxDynamicSharedMemorySize, SMEM1);
    cudaFuncSetAttribute(edge_kernel,  cudaFuncAttributeMaxDynamicSharedMemorySize, SMEM2);
    cudaFuncSetAttribute(node_kernel,  cudaFuncAttributeMaxDynamicSharedMemorySize, SMEM3);

    void* aggPtr = nullptr;
    cudaGetSymbolAddress(&aggPtr, g_agg);
    cudaMemsetAsync(aggPtr, 0, (size_t)N * D * sizeof(float));
    void* flagPtr = nullptr;
    cudaGetSymbolAddress(&flagPtr, g_oddor);
    cudaMemsetAsync(flagPtr, 0, sizeof(int));

    probe_kernel<<<1, 256>>>((const int*)eraw);
    pack_kernel<<<32, 256>>>(W2);
    pack_node_kernel<<<128, 256>>>(U1, U2);
    gemm1_kernel<<<152, 512, SMEM1>>>(h, W1, U1, N);
    edge_kernel<<<444, 256, SMEM2>>>(coords, eraw, W1, b1, b2, N, E);
    node_kernel<<<304, 512, SMEM3>>>(h, c1, c2, (float*)d_out, N);
}

// round 15
// speedup vs baseline: 1.1795x; 1.1427x over previous
#include <cuda_runtime.h>
#include <cstdint>
#include <cstdio>

#define D 128
#define MAXN 50000
#define LDA 132   // padded lead dim (floats) for tf32 mma fragment loads
#define LDT 68    // padded lead dim (bf16x2 words) for edge t tile

// Scratch (device globals: allocation-free contract). 16B-aligned for vector ld/st.
__device__ __align__(16) float g_PQR[(size_t)MAXN * 384];  // [N][384]: P=h@W1a^T, Q=h@W1b^T, R=h@U1a^T
__device__ __align__(16) float g_agg[(size_t)MAXN * D];    // scatter-add target
__device__ __align__(16) uint4 g_W2pack[8 * 4 * 2 * 32];   // bf16 B-frags for edge GEMM2 (coalesced)
__device__ __align__(16) uint4 g_Upack[2 * 16 * 2 * 4 * 32];   // tf32 B-frags for node GEMMs (131KB)
__device__ __align__(16) uint4 g_Wcatpack[16 * 12 * 2 * 32];   // tf32 B-frags for gemm1 (196KB)
__device__ int g_oddor;                                     // OR of odd 32-bit words of edge buffer

__device__ __forceinline__ unsigned f2tf(float x){
    unsigned u; asm("cvt.rna.tf32.f32 %0, %1;" : "=r"(u) : "f"(x)); return u;
}
__device__ __forceinline__ unsigned f2bf2(float lo, float hi){
    unsigned u; asm("cvt.rn.bf16x2.f32 %0, %1, %2;" : "=r"(u) : "f"(hi), "f"(lo)); return u;
}
__device__ __forceinline__ float silu(float x){           // exact-ish (2 MUFU)
    return x * (1.0f / (1.0f + __expf(-x)));
}
__device__ __forceinline__ float silu_fast(float x){      // 1 MUFU via hw tanh
    float hx = 0.5f * x;
    float t; asm("tanh.approx.f32 %0, %1;" : "=f"(t) : "f"(hx));
    return hx + hx * t;                                   // 0.5x(1+tanh(x/2))
}
__device__ __forceinline__ void mma8(float* c, const unsigned* a, const unsigned* b){
    asm volatile(
      "mma.sync.aligned.m16n8k8.row.col.f32.tf32.tf32.f32 "
      "{%0,%1,%2,%3},{%4,%5,%6,%7},{%8,%9},{%0,%1,%2,%3};\n"
      : "+f"(c[0]), "+f"(c[1]), "+f"(c[2]), "+f"(c[3])
      : "r"(a[0]), "r"(a[1]), "r"(a[2]), "r"(a[3]), "r"(b[0]), "r"(b[1]));
}
__device__ __forceinline__ void mma16(float* c, const unsigned* a, const unsigned* b){
    asm volatile(
      "mma.sync.aligned.m16n8k16.row.col.f32.bf16.bf16.f32 "
      "{%0,%1,%2,%3},{%4,%5,%6,%7},{%8,%9},{%0,%1,%2,%3};\n"
      : "+f"(c[0]), "+f"(c[1]), "+f"(c[2]), "+f"(c[3])
      : "r"(a[0]), "r"(a[1]), "r"(a[2]), "r"(a[3]), "r"(b[0]), "r"(b[1]));
}
__device__ __forceinline__ void red4(float* addr, float x, float y, float z, float w){
    asm volatile("red.global.add.v4.f32 [%0], {%1,%2,%3,%4};"
                 :: "l"(addr), "f"(x), "f"(y), "f"(z), "f"(w) : "memory");
}

// ---------------------------------------------------------------------------
// Probe: detect edge_index element width (int64 hi-words all zero vs int32).
// ---------------------------------------------------------------------------
__global__ void probe_kernel(const int* __restrict__ ebuf)
{
    int v = 0;
    for (int i = threadIdx.x; i < 4096; i += blockDim.x)
        v |= ebuf[2 * i + 1];
    if (v) atomicOr(&g_oddor, v);
}

// ---------------------------------------------------------------------------
// Pack W2 into warp-coalesced bf16 B-fragment entries for m16n8k16 (R12 layout).
// ---------------------------------------------------------------------------
__global__ void pack_kernel(const float* __restrict__ W2)
{
    int idx = blockIdx.x * 256 + threadIdx.x;   // word index
    if (idx >= 8 * 4 * 2 * 32 * 4) return;
    int wd   = idx & 3;
    int lane = (idx >> 2) & 31;
    int np   = (idx >> 7) & 1;
    int wcc  = (idx >> 8) & 3;
    int ks   = idx >> 10;
    int nf = np * 2 + (wd >> 1);
    int r  = wd & 1;
    int row = wcc * 32 + nf * 8 + (lane >> 2);
    int k0  = ks * 16 + (lane & 3) * 2 + r * 8;
    ((unsigned*)g_W2pack)[idx] = f2bf2(W2[row * D + k0], W2[row * D + k0 + 1]);
}

// ---------------------------------------------------------------------------
// Pack U1b (L=0) and U2 (L=1) into warp-coalesced tf32 B-frag entries for mma8.
// ---------------------------------------------------------------------------
__global__ void pack_node_kernel(const float* __restrict__ U1,
                                 const float* __restrict__ U2)
{
    int idx = blockIdx.x * 256 + threadIdx.x;   // word index, 32768 total
    if (idx >= 2 * 16 * 2 * 4 * 32 * 4) return;
    int wd   = idx & 3;
    int lane = (idx >> 2) & 31;
    int np   = (idx >> 7) & 3;
    int wc   = (idx >> 9) & 1;
    int ks   = (idx >> 10) & 15;
    int L    = (idx >> 14) & 1;
    int nf = np * 2 + (wd >> 1);
    int r  = wd & 1;
    int row = wc * 64 + nf * 8 + (lane >> 2);
    int col = ks * 8 + (lane & 3) + r * 4;
    float v = (L == 0) ? U1[row * 256 + 128 + col] : U2[row * D + col];
    ((unsigned*)g_Upack)[idx] = f2tf(v);
}

// ---------------------------------------------------------------------------
// Pack Wcat (rows 0..127 = W1[:, :128], 128..255 = W1[:,128:256],
// 256..383 = U1[:, :128]) into warp-coalesced tf32 B-frag entries for gemm1:
// word addr = (((ks*12+cg)*2+np)*32+lane)*4+wd
//   nf = np*2 + (wd>>1), r = wd&1
//   row = cg*32 + nf*8 + (lane>>2), col = ks*8 + (lane&3) + r*4
// ---------------------------------------------------------------------------
__global__ void pack_gemm1_kernel(const float* __restrict__ W1,
                                  const float* __restrict__ U1)
{
    int idx = blockIdx.x * 256 + threadIdx.x;   // word index, 49152 total
    if (idx >= 16 * 12 * 2 * 32 * 4) return;
    int wd   = idx & 3;
    int lane = (idx >> 2) & 31;
    int np   = (idx >> 7) & 1;
    int cg   = (idx >> 8) % 12;
    int ks   = (idx >> 8) / 12;
    int nf = np * 2 + (wd >> 1);
    int r  = wd & 1;
    int row = cg * 32 + nf * 8 + (lane >> 2);
    int col = ks * 8 + (lane & 3) + r * 4;
    float v;
    if (row < 128)      v = W1[row * 257 + col];
    else if (row < 256) v = W1[(row - 128) * 257 + 128 + col];
    else                v = U1[(row - 256) * 256 + col];
    ((unsigned*)g_Wcatpack)[idx] = f2tf(v);
}

// ---------------------------------------------------------------------------
// Kernel 1 v2: PQR = h @ Wcat^T. 384 threads, tile 32 rows x 384 cols.
// Weights from L2-resident g_Wcatpack; smem = sA only (17KB) -> 2+ CTAs/SM.
// 12 warps: warp w = col group (32 cols), mf=2 x nf=4.
// ---------------------------------------------------------------------------
__global__ __launch_bounds__(384, 2) void gemm1_kernel(
    const float* __restrict__ h, int N)
{
    extern __shared__ unsigned sm[];
    unsigned* sA = sm;               // 32*LDA
    int tid = threadIdx.x;

    int w = tid >> 5, l = tid & 31, g = l >> 2, t4 = l & 3;
    int ntiles = (N + 31) >> 5;

    for (int tt = blockIdx.x; tt < ntiles; tt += gridDim.x) {
        __syncthreads();
        int row0 = tt << 5;
        // tile load: 32 rows x 32 quads = 1024 quads over 384 threads
        for (int idx = tid; idx < 1024; idx += 384) {
            int r = idx >> 5, q = idx & 31;
            int i = row0 + r;
            float4 v = make_float4(0.f, 0.f, 0.f, 0.f);
            if (i < N) v = *(const float4*)&h[(size_t)i * D + q * 4];
            uint4 u = make_uint4(f2tf(v.x), f2tf(v.y), f2tf(v.z), f2tf(v.w));
            *(uint4*)&sA[r * LDA + q * 4] = u;
        }
        __syncthreads();

        float acc[2][4][4];
        #pragma unroll
        for (int mf = 0; mf < 2; mf++)
            #pragma unroll
            for (int nf = 0; nf < 4; nf++)
                #pragma unroll
                for (int q = 0; q < 4; q++) acc[mf][nf][q] = 0.f;

        #pragma unroll
        for (int ks = 0; ks < 16; ++ks) {
            int kb = ks * 8;
            unsigned a[2][4];
            #pragma unroll
            for (int mf = 0; mf < 2; mf++) {
                int r0 = mf * 16 + g;
                a[mf][0] = sA[r0 * LDA + kb + t4];
                a[mf][1] = sA[(r0 + 8) * LDA + kb + t4];
                a[mf][2] = sA[r0 * LDA + kb + t4 + 4];
                a[mf][3] = sA[(r0 + 8) * LDA + kb + t4 + 4];
            }
            // 2 coalesced LDG.128 per ks (512B/warp), L2-resident
            uint4 q0 = g_Wcatpack[((ks * 12 + w) * 2 + 0) * 32 + l];
            uint4 q1 = g_Wcatpack[((ks * 12 + w) * 2 + 1) * 32 + l];
            unsigned bb[8] = { q0.x, q0.y, q0.z, q0.w, q1.x, q1.y, q1.z, q1.w };
            #pragma unroll
            for (int nf = 0; nf < 4; nf++) {
                mma8(acc[0][nf], a[0], &bb[nf * 2]);
                mma8(acc[1][nf], a[1], &bb[nf * 2]);
            }
        }
        #pragma unroll
        for (int mf = 0; mf < 2; mf++) {
            int i0 = row0 + mf * 16 + g;
            int i1 = i0 + 8;
            #pragma unroll
            for (int nf = 0; nf < 4; nf++) {
                int col = w * 32 + nf * 8 + t4 * 2;
                if (i0 < N) *(float2*)&g_PQR[(size_t)i0 * 384 + col] = make_float2(acc[mf][nf][0], acc[mf][nf][1]);
                if (i1 < N) *(float2*)&g_PQR[(size_t)i1 * 384 + col] = make_float2(acc[mf][nf][2], acc[mf][nf][3]);
            }
        }
    }
}

// ---------------------------------------------------------------------------
// Kernel 2: edge kernel (R12 structure, single sT, 2 syncs/tile, hoisted vrec).
// Tile = 64 edges, 256 threads, 3 CTAs/SM.
// ---------------------------------------------------------------------------
__global__ __launch_bounds__(256, 3) void edge_kernel(
    const float* __restrict__ coords, const void* __restrict__ eraw,
    const float* __restrict__ W1, const float* __restrict__ b1,
    const float* __restrict__ b2, int N, int E)
{
    extern __shared__ unsigned sm[];
    unsigned* sT  = sm;              // 64*LDT words (bf16x2 t tile)
    float* sb1   = (float*)(sT + 64 * LDT);
    float* sb2   = sb1 + 128;
    float* swc   = sb2 + 128;
    int tid = threadIdx.x;

    const bool is64 = (g_oddor == 0);
    const int*       e32 = (const int*)eraw;
    const long long* e64 = (const long long*)eraw;

    if (tid < 128) { sb1[tid] = b1[tid]; sb2[tid] = b2[tid]; swc[tid] = W1[tid * 257 + 256]; }
    __syncthreads();

    int w = tid >> 5, l = tid & 31, g = l >> 2, t4 = l & 3;
    int wr = w & 1, wcc = w >> 1;     // 2 row-groups (32 rows) x 4 col-groups (32 cols)
    int ntiles = (E + 63) >> 6;

    for (int tt = blockIdx.x; tt < ntiles; tt += gridDim.x) {
        int e0 = tt << 6;

        // ---- build t tile (bf16x2): each warp covers edges w, w+8, ..., w+56 ----
        #pragma unroll
        for (int half = 0; half < 2; ++half) {
            float4 pv[4], qv[4]; float dv[4]; int el[4];
            #pragma unroll
            for (int it = 0; it < 4; ++it) {
                int e_loc = w + (half * 4 + it) * 8;
                el[it] = e_loc;
                int e = e0 + e_loc;
                int v = 0;
                if (l < 2 && e < E)
                    v = is64 ? (int)e64[(size_t)l * E + e] : e32[(size_t)l * E + e];
                int s = __shfl_sync(0xffffffffu, v, 0);
                int r = __shfl_sync(0xffffffffu, v, 1);
                if ((unsigned)s >= (unsigned)N) s = 0;
                if ((unsigned)r >= (unsigned)N) r = 0;
                float cd = 0.f;
                if (l < 3) cd = coords[s * 3 + l] - coords[r * 3 + l];
                float dx = __shfl_sync(0xffffffffu, cd, 0);
                float dy = __shfl_sync(0xffffffffu, cd, 1);
                float dz = __shfl_sync(0xffffffffu, cd, 2);
                dv[it] = sqrtf(dx * dx + dy * dy + dz * dz);
                pv[it] = *(const float4*)&g_PQR[(size_t)s * 384 + l * 4];
                qv[it] = *(const float4*)&g_PQR[(size_t)r * 384 + 128 + l * 4];
            }
            #pragma unroll
            for (int it = 0; it < 4; ++it) {
                int c = l * 4;
                float x0 = pv[it].x + qv[it].x + dv[it] * swc[c + 0] + sb1[c + 0];
                float x1 = pv[it].y + qv[it].y + dv[it] * swc[c + 1] + sb1[c + 1];
                float x2 = pv[it].z + qv[it].z + dv[it] * swc[c + 2] + sb1[c + 2];
                float x3 = pv[it].w + qv[it].w + dv[it] * swc[c + 3] + sb1[c + 3];
                uint2 st = make_uint2(f2bf2(silu_fast(x0), silu_fast(x1)),
                                      f2bf2(silu_fast(x2), silu_fast(x3)));
                *(uint2*)&sT[el[it] * LDT + l * 2] = st;
            }
        }
        __syncthreads();

        // hoisted receiver-index load: latency hides under the mma loop
        int rowlane = wr * 32 + l;     // this warp's 32 tile-rows
        int vrec = 0;
        if (e0 + rowlane < E)
            vrec = is64 ? (int)e64[(size_t)E + e0 + rowlane] : e32[(size_t)E + e0 + rowlane];
        if ((unsigned)vrec >= (unsigned)N) vrec = 0;

        // ---- GEMM2 (bf16): warp computes 32 rows (wr) x 32 cols (wcc) ----
        float acc[2][4][4];
        #pragma unroll
        for (int mf = 0; mf < 2; mf++)
            #pragma unroll
            for (int nf = 0; nf < 4; nf++)
                #pragma unroll
                for (int q = 0; q < 4; q++) acc[mf][nf][q] = 0.f;

        #pragma unroll
        for (int ks = 0; ks < 8; ++ks) {
            int kw = ks * 8;            // 8 bf16x2 words = 16 k-cols per step
            unsigned a[2][4];
            #pragma unroll
            for (int mf = 0; mf < 2; mf++) {
                int r0 = wr * 32 + mf * 16 + g;
                a[mf][0] = sT[r0 * LDT + kw + t4];
                a[mf][1] = sT[(r0 + 8) * LDT + kw + t4];
                a[mf][2] = sT[r0 * LDT + kw + t4 + 4];
                a[mf][3] = sT[(r0 + 8) * LDT + kw + t4 + 4];
            }
            uint4 q0 = g_W2pack[((ks * 4 + wcc) * 2 + 0) * 32 + l];
            uint4 q1 = g_W2pack[((ks * 4 + wcc) * 2 + 1) * 32 + l];
            unsigned bb[8] = { q0.x, q0.y, q0.z, q0.w, q1.x, q1.y, q1.z, q1.w };
            #pragma unroll
            for (int nf = 0; nf < 4; nf++) {
                mma16(acc[0][nf], a[0], &bb[nf * 2]);
                mma16(acc[1][nf], a[1], &bb[nf * 2]);
            }
        }
        __syncthreads();   // sT free for next tile's t-build

        // ---- scatter direct from regs: bias + silu, shfl-pair -> red.v4 ----
        #pragma unroll
        for (int mf = 0; mf < 2; mf++) {
            #pragma unroll
            for (int hh = 0; hh < 2; ++hh) {
                int rsel = mf * 16 + hh * 8 + g;
                int rec = __shfl_sync(0xffffffffu, vrec, rsel);
                bool valid = (e0 + wr * 32 + rsel) < E;
                #pragma unroll
                for (int nf = 0; nf < 4; nf++) {
                    int col = wcc * 32 + nf * 8 + t4 * 2;
                    float m0 = silu_fast(acc[mf][nf][hh * 2]     + sb2[col]);
                    float m1 = silu_fast(acc[mf][nf][hh * 2 + 1] + sb2[col + 1]);
                    // lane t4^1 holds the adjacent column pair
                    float n0 = __shfl_xor_sync(0xffffffffu, m0, 1);
                    float n1 = __shfl_xor_sync(0xffffffffu, m1, 1);
                    if (((t4 & 1) == 0) && valid) {
                        int cb = wcc * 32 + nf * 8 + (t4 >> 1) * 4;  // t4=0 -> +0, t4=2 -> +4
                        red4(&g_agg[(size_t)rec * D + cb], m0, m1, n0, n1);
                    }
                }
            }
        }
    }
}

// ---------------------------------------------------------------------------
// Kernel 3: node update v2. 512 threads, tile 128 nodes, 2 CTAs/SM.
// Weights from L2-resident g_Upack; tf32 + exact silu.
// ---------------------------------------------------------------------------
__global__ __launch_bounds__(512, 2) void node_kernel(
    const float* __restrict__ h, const float* __restrict__ c1,
    const float* __restrict__ c2, float* __restrict__ out, int N)
{
    extern __shared__ unsigned sm[];
    unsigned* sA = sm;               // 128*LDA (agg tile, then t tile)
    float* sc1 = (float*)(sA + 128 * LDA);
    float* sc2 = sc1 + 128;
    int tid = threadIdx.x;

    if (tid < 128) { sc1[tid] = c1[tid]; sc2[tid] = c2[tid]; }

    int w = tid >> 5, l = tid & 31, g = l >> 2, t4 = l & 3;
    int wr = w >> 1, wc = w & 1;
    int ntiles = (N + 127) >> 7;

    for (int tt = blockIdx.x; tt < ntiles; tt += gridDim.x) {
        __syncthreads();
        int n0 = tt << 7;
        #pragma unroll
        for (int it = 0; it < 8; ++it) {
            int idx = tid + it * 512;
            int r = idx >> 5, q = idx & 31;
            int i = n0 + r;
            float4 v = make_float4(0.f, 0.f, 0.f, 0.f);
            if (i < N) v = *(const float4*)&g_agg[(size_t)i * D + q * 4];
            uint4 u = make_uint4(f2tf(v.x), f2tf(v.y), f2tf(v.z), f2tf(v.w));
            *(uint4*)&sA[r * LDA + q * 4] = u;
        }
        __syncthreads();

        float acc[8][4];
        #pragma unroll
        for (int nf = 0; nf < 8; nf++)
            #pragma unroll
            for (int q = 0; q < 4; q++) acc[nf][q] = 0.f;

        #pragma unroll
        for (int ks = 0; ks < 16; ++ks) {
            int kb = ks * 8;
            unsigned a[4];
            int r0 = wr * 16 + g;
            a[0] = sA[r0 * LDA + kb + t4];
            a[1] = sA[(r0 + 8) * LDA + kb + t4];
            a[2] = sA[r0 * LDA + kb + t4 + 4];
            a[3] = sA[(r0 + 8) * LDA + kb + t4 + 4];
            const uint4* up = &g_Upack[(((0 * 16 + ks) * 2 + wc) * 4) * 32 + l];
            uint4 q0 = up[0], q1 = up[32], q2 = up[64], q3 = up[96];
            unsigned bb[16] = { q0.x,q0.y,q0.z,q0.w, q1.x,q1.y,q1.z,q1.w,
                                q2.x,q2.y,q2.z,q2.w, q3.x,q3.y,q3.z,q3.w };
            #pragma unroll
            for (int nf = 0; nf < 8; nf++)
                mma8(acc[nf], a, &bb[nf * 2]);
        }
        __syncthreads();  // all warps done reading agg tile before overwrite with t

        int rA = wr * 16 + g;
        int i0 = n0 + rA, i1 = i0 + 8;
        #pragma unroll
        for (int nf = 0; nf < 8; nf++) {
            int col = wc * 64 + nf * 8 + t4 * 2;
            float r00 = 0.f, r01 = 0.f, r10 = 0.f, r11 = 0.f;
            if (i0 < N) { float2 rv = *(const float2*)&g_PQR[(size_t)i0 * 384 + 256 + col]; r00 = rv.x; r01 = rv.y; }
            if (i1 < N) { float2 rv = *(const float2*)&g_PQR[(size_t)i1 * 384 + 256 + col]; r10 = rv.x; r11 = rv.y; }
            sA[rA * LDA + col]           = f2tf(silu(acc[nf][0] + r00 + sc1[col]));
            sA[rA * LDA + col + 1]       = f2tf(silu(acc[nf][1] + r01 + sc1[col + 1]));
            sA[(rA + 8) * LDA + col]     = f2tf(silu(acc[nf][2] + r10 + sc1[col]));
            sA[(rA + 8) * LDA + col + 1] = f2tf(silu(acc[nf][3] + r11 + sc1[col + 1]));
        }
        __syncthreads();

        float acc2[8][4];
        #pragma unroll
        for (int nf = 0; nf < 8; nf++)
            #pragma unroll
            for (int q = 0; q < 4; q++) acc2[nf][q] = 0.f;

        #pragma unroll
        for (int ks = 0; ks < 16; ++ks) {
            int kb = ks * 8;
            unsigned a[4];
            int r0 = wr * 16 + g;
            a[0] = sA[r0 * LDA + kb + t4];
            a[1] = sA[(r0 + 8) * LDA + kb + t4];
            a[2] = sA[r0 * LDA + kb + t4 + 4];
            a[3] = sA[(r0 + 8) * LDA + kb + t4 + 4];
            const uint4* up = &g_Upack[(((1 * 16 + ks) * 2 + wc) * 4) * 32 + l];
            uint4 q0 = up[0], q1 = up[32], q2 = up[64], q3 = up[96];
            unsigned bb[16] = { q0.x,q0.y,q0.z,q0.w, q1.x,q1.y,q1.z,q1.w,
                                q2.x,q2.y,q2.z,q2.w, q3.x,q3.y,q3.z,q3.w };
            #pragma unroll
            for (int nf = 0; nf < 8; nf++)
                mma8(acc2[nf], a, &bb[nf * 2]);
        }

        #pragma unroll
        for (int nf = 0; nf < 8; nf++) {
            int col = wc * 64 + nf * 8 + t4 * 2;
            if (i0 < N) {
                float2 hv = *(const float2*)&h[(size_t)i0 * D + col];
                *(float2*)&out[(size_t)i0 * D + col] =
                    make_float2(hv.x + acc2[nf][0] + sc2[col], hv.y + acc2[nf][1] + sc2[col + 1]);
            }
            if (i1 < N) {
                float2 hv = *(const float2*)&h[(size_t)i1 * D + col];
                *(float2*)&out[(size_t)i1 * D + col] =
                    make_float2(hv.x + acc2[nf][2] + sc2[col], hv.y + acc2[nf][3] + sc2[col + 1]);
            }
        }
    }
}

// ---------------------------------------------------------------------------
extern "C" void kernel_launch(void* const* d_in, const int* in_sizes, int n_in,
                              void* d_out, int out_size)
{
    const float* h      = (const float*)d_in[0];
    const float* coords = (const float*)d_in[1];
    const void*  eraw   = (const void*)d_in[2];
    const float* W1     = (const float*)d_in[3];
    const float* b1     = (const float*)d_in[4];
    const float* W2     = (const float*)d_in[5];
    const float* b2     = (const float*)d_in[6];
    const float* U1     = (const float*)d_in[7];
    const float* c1     = (const float*)d_in[8];
    const float* U2     = (const float*)d_in[9];
    const float* c2     = (const float*)d_in[10];

    int N = in_sizes[0] / D;
    int E = in_sizes[2] / 2;
    if (N > MAXN) N = MAXN;

    const int SMEM1 = 32 * LDA * 4;                 // 16,896
    const int SMEM2 = 64 * LDT * 4 + 3 * 128 * 4;   // 18,944
    const int SMEM3 = 128 * LDA * 4 + 2 * 128 * 4;  // 68,608

    cudaFuncSetAttribute(gemm1_kernel, cudaFuncAttributeMaxDynamicSharedMemorySize, SMEM1);
    cudaFuncSetAttribute(edge_kernel,  cudaFuncAttributeMaxDynamicSharedMemorySize, SMEM2);
    cudaFuncSetAttribute(node_kernel,  cudaFuncAttributeMaxDynamicSharedMemorySize, SMEM3);

    void* aggPtr = nullptr;
    cudaGetSymbolAddress(&aggPtr, g_agg);
    cudaMemsetAsync(aggPtr, 0, (size_t)N * D * sizeof(float));
    void* flagPtr = nullptr;
    cudaGetSymbolAddress(&flagPtr, g_oddor);
    cudaMemsetAsync(flagPtr, 0, sizeof(int));

    probe_kernel<<<1, 256>>>((const int*)eraw);
    pack_kernel<<<32, 256>>>(W2);
    pack_node_kernel<<<128, 256>>>(U1, U2);
    pack_gemm1_kernel<<<192, 256>>>(W1, U1);
    gemm1_kernel<<<304, 384, SMEM1>>>(h, N);
    edge_kernel<<<444, 256, SMEM2>>>(coords, eraw, W1, b1, b2, N, E);
    node_kernel<<<304, 512, SMEM3>>>(h, c1, c2, (float*)d_out, N);
}

// round 16
// speedup vs baseline: 1.2194x; 1.0338x over previous
#include <cuda_runtime.h>
#include <cstdint>
#include <cstdio>

#define D 128
#define MAXN 50000
#define MAXE 800000
#define LDA 132   // padded lead dim (floats) for tf32 mma fragment loads
#define LDT 68    // padded lead dim (bf16x2 words) for edge t tile
#define GRIDE 444
#define GRIDG 304

// Scratch (device globals: allocation-free contract). 16B-aligned for vector ld/st.
__device__ __align__(16) float g_PQR[(size_t)MAXN * 384];  // [N][384]: P=h@W1a^T, Q=h@W1b^T, R=h@U1a^T
__device__ __align__(16) float g_agg[(size_t)MAXN * D];    // scatter-add target
__device__ __align__(16) uint4 g_edgeT[MAXE];              // per-edge {s, r, dist_bits, 0}
__device__ __align__(16) uint4 g_W2pack[8 * 4 * 2 * 32];   // bf16 B-frags for edge GEMM2 (coalesced)
__device__ __align__(16) uint4 g_Upack[2 * 16 * 2 * 4 * 32];   // tf32 B-frags for node GEMMs (131KB)
__device__ __align__(16) uint4 g_Wcatpack[16 * 12 * 2 * 32];   // tf32 B-frags for gemm1 (196KB)
__device__ int g_oddor;                                     // OR of odd 32-bit words of edge buffer
__device__ unsigned g_tick_e, g_tick_g;                     // dynamic tile tickets

__device__ __forceinline__ unsigned f2tf(float x){
    unsigned u; asm("cvt.rna.tf32.f32 %0, %1;" : "=r"(u) : "f"(x)); return u;
}
__device__ __forceinline__ unsigned f2bf2(float lo, float hi){
    unsigned u; asm("cvt.rn.bf16x2.f32 %0, %1, %2;" : "=r"(u) : "f"(hi), "f"(lo)); return u;
}
__device__ __forceinline__ float silu(float x){           // exact-ish (2 MUFU)
    return x * (1.0f / (1.0f + __expf(-x)));
}
__device__ __forceinline__ float silu_fast(float x){      // 1 MUFU via hw tanh
    float hx = 0.5f * x;
    float t; asm("tanh.approx.f32 %0, %1;" : "=f"(t) : "f"(hx));
    return hx + hx * t;                                   // 0.5x(1+tanh(x/2))
}
__device__ __forceinline__ void mma8(float* c, const unsigned* a, const unsigned* b){
    asm volatile(
      "mma.sync.aligned.m16n8k8.row.col.f32.tf32.tf32.f32 "
      "{%0,%1,%2,%3},{%4,%5,%6,%7},{%8,%9},{%0,%1,%2,%3};\n"
      : "+f"(c[0]), "+f"(c[1]), "+f"(c[2]), "+f"(c[3])
      : "r"(a[0]), "r"(a[1]), "r"(a[2]), "r"(a[3]), "r"(b[0]), "r"(b[1]));
}
__device__ __forceinline__ void mma16(float* c, const unsigned* a, const unsigned* b){
    asm volatile(
      "mma.sync.aligned.m16n8k16.row.col.f32.bf16.bf16.f32 "
      "{%0,%1,%2,%3},{%4,%5,%6,%7},{%8,%9},{%0,%1,%2,%3};\n"
      : "+f"(c[0]), "+f"(c[1]), "+f"(c[2]), "+f"(c[3])
      : "r"(a[0]), "r"(a[1]), "r"(a[2]), "r"(a[3]), "r"(b[0]), "r"(b[1]));
}
__device__ __forceinline__ void red4(float* addr, float x, float y, float z, float w){
    asm volatile("red.global.add.v4.f32 [%0], {%1,%2,%3,%4};"
                 :: "l"(addr), "f"(x), "f"(y), "f"(z), "f"(w) : "memory");
}

// ---------------------------------------------------------------------------
// Probe: detect edge_index element width; also reset the tile tickets.
// ---------------------------------------------------------------------------
__global__ void probe_kernel(const int* __restrict__ ebuf)
{
    if (blockIdx.x == 0 && threadIdx.x == 0) { g_tick_e = GRIDE; g_tick_g = GRIDG; }
    int v = 0;
    for (int i = threadIdx.x; i < 4096; i += blockDim.x)
        v |= ebuf[2 * i + 1];
    if (v) atomicOr(&g_oddor, v);
}

// ---------------------------------------------------------------------------
// Prep: per-edge table {sender, receiver, dist}. Runs once per launch.
// ---------------------------------------------------------------------------
__global__ void prep_edge_kernel(const float* __restrict__ coords,
                                 const void* __restrict__ eraw, int N, int E)
{
    int e = blockIdx.x * 256 + threadIdx.x;
    if (e >= E) return;
    const bool is64 = (g_oddor == 0);
    int s, r;
    if (is64) { s = (int)((const long long*)eraw)[e]; r = (int)((const long long*)eraw)[(size_t)E + e]; }
    else      { s = ((const int*)eraw)[e];            r = ((const int*)eraw)[(size_t)E + e]; }
    if ((unsigned)s >= (unsigned)N) s = 0;
    if ((unsigned)r >= (unsigned)N) r = 0;
    float dx = coords[s * 3 + 0] - coords[r * 3 + 0];
    float dy = coords[s * 3 + 1] - coords[r * 3 + 1];
    float dz = coords[s * 3 + 2] - coords[r * 3 + 2];
    float dd = sqrtf(dx * dx + dy * dy + dz * dz);
    g_edgeT[e] = make_uint4((unsigned)s, (unsigned)r, __float_as_uint(dd), 0u);
}

// ---------------------------------------------------------------------------
// Pack W2 into warp-coalesced bf16 B-fragment entries for m16n8k16 (R12 layout).
// ---------------------------------------------------------------------------
__global__ void pack_kernel(const float* __restrict__ W2)
{
    int idx = blockIdx.x * 256 + threadIdx.x;   // word index
    if (idx >= 8 * 4 * 2 * 32 * 4) return;
    int wd   = idx & 3;
    int lane = (idx >> 2) & 31;
    int np   = (idx >> 7) & 1;
    int wcc  = (idx >> 8) & 3;
    int ks   = idx >> 10;
    int nf = np * 2 + (wd >> 1);
    int r  = wd & 1;
    int row = wcc * 32 + nf * 8 + (lane >> 2);
    int k0  = ks * 16 + (lane & 3) * 2 + r * 8;
    ((unsigned*)g_W2pack)[idx] = f2bf2(W2[row * D + k0], W2[row * D + k0 + 1]);
}

// ---------------------------------------------------------------------------
// Pack U1b (L=0) and U2 (L=1) into warp-coalesced tf32 B-frag entries for mma8.
// ---------------------------------------------------------------------------
__global__ void pack_node_kernel(const float* __restrict__ U1,
                                 const float* __restrict__ U2)
{
    int idx = blockIdx.x * 256 + threadIdx.x;   // word index, 32768 total
    if (idx >= 2 * 16 * 2 * 4 * 32 * 4) return;
    int wd   = idx & 3;
    int lane = (idx >> 2) & 31;
    int np   = (idx >> 7) & 3;
    int wc   = (idx >> 9) & 1;
    int ks   = (idx >> 10) & 15;
    int L    = (idx >> 14) & 1;
    int nf = np * 2 + (wd >> 1);
    int r  = wd & 1;
    int row = wc * 64 + nf * 8 + (lane >> 2);
    int col = ks * 8 + (lane & 3) + r * 4;
    float v = (L == 0) ? U1[row * 256 + 128 + col] : U2[row * D + col];
    ((unsigned*)g_Upack)[idx] = f2tf(v);
}

// ---------------------------------------------------------------------------
// Pack Wcat into warp-coalesced tf32 B-frag entries for gemm1 (R15 layout).
// ---------------------------------------------------------------------------
__global__ void pack_gemm1_kernel(const float* __restrict__ W1,
                                  const float* __restrict__ U1)
{
    int idx = blockIdx.x * 256 + threadIdx.x;   // word index, 49152 total
    if (idx >= 16 * 12 * 2 * 32 * 4) return;
    int wd   = idx & 3;
    int lane = (idx >> 2) & 31;
    int np   = (idx >> 7) & 1;
    int cg   = (idx >> 8) % 12;
    int ks   = (idx >> 8) / 12;
    int nf = np * 2 + (wd >> 1);
    int r  = wd & 1;
    int row = cg * 32 + nf * 8 + (lane >> 2);
    int col = ks * 8 + (lane & 3) + r * 4;
    float v;
    if (row < 128)      v = W1[row * 257 + col];
    else if (row < 256) v = W1[(row - 128) * 257 + 128 + col];
    else                v = U1[(row - 256) * 256 + col];
    ((unsigned*)g_Wcatpack)[idx] = f2tf(v);
}

// ---------------------------------------------------------------------------
// Kernel 1 v3: PQR = h @ Wcat^T. 384 threads, tile 32 rows x 384 cols.
// Packed weights + dynamic tickets.
// ---------------------------------------------------------------------------
__global__ __launch_bounds__(384, 2) void gemm1_kernel(
    const float* __restrict__ h, int N)
{
    extern __shared__ unsigned sm[];
    unsigned* sA = sm;               // 32*LDA
    __shared__ int sNext;
    int tid = threadIdx.x;

    int w = tid >> 5, l = tid & 31, g = l >> 2, t4 = l & 3;
    int ntiles = (N + 31) >> 5;

    int tt = blockIdx.x;
    while (tt < ntiles) {
        if (tid == 0) sNext = (int)atomicAdd(&g_tick_g, 1u);
        __syncthreads();     // prev-iter sA reads done; sNext visible
        int ttn = sNext;
        int row0 = tt << 5;
        for (int idx = tid; idx < 1024; idx += 384) {
            int r = idx >> 5, q = idx & 31;
            int i = row0 + r;
            float4 v = make_float4(0.f, 0.f, 0.f, 0.f);
            if (i < N) v = *(const float4*)&h[(size_t)i * D + q * 4];
            uint4 u = make_uint4(f2tf(v.x), f2tf(v.y), f2tf(v.z), f2tf(v.w));
            *(uint4*)&sA[r * LDA + q * 4] = u;
        }
        __syncthreads();

        float acc[2][4][4];
        #pragma unroll
        for (int mf = 0; mf < 2; mf++)
            #pragma unroll
            for (int nf = 0; nf < 4; nf++)
                #pragma unroll
                for (int q = 0; q < 4; q++) acc[mf][nf][q] = 0.f;

        #pragma unroll
        for (int ks = 0; ks < 16; ++ks) {
            int kb = ks * 8;
            unsigned a[2][4];
            #pragma unroll
            for (int mf = 0; mf < 2; mf++) {
                int r0 = mf * 16 + g;
                a[mf][0] = sA[r0 * LDA + kb + t4];
                a[mf][1] = sA[(r0 + 8) * LDA + kb + t4];
                a[mf][2] = sA[r0 * LDA + kb + t4 + 4];
                a[mf][3] = sA[(r0 + 8) * LDA + kb + t4 + 4];
            }
            uint4 q0 = g_Wcatpack[((ks * 12 + w) * 2 + 0) * 32 + l];
            uint4 q1 = g_Wcatpack[((ks * 12 + w) * 2 + 1) * 32 + l];
            unsigned bb[8] = { q0.x, q0.y, q0.z, q0.w, q1.x, q1.y, q1.z, q1.w };
            #pragma unroll
            for (int nf = 0; nf < 4; nf++) {
                mma8(acc[0][nf], a[0], &bb[nf * 2]);
                mma8(acc[1][nf], a[1], &bb[nf * 2]);
            }
        }
        #pragma unroll
        for (int mf = 0; mf < 2; mf++) {
            int i0 = row0 + mf * 16 + g;
            int i1 = i0 + 8;
            #pragma unroll
            for (int nf = 0; nf < 4; nf++) {
                int col = w * 32 + nf * 8 + t4 * 2;
                if (i0 < N) *(float2*)&g_PQR[(size_t)i0 * 384 + col] = make_float2(acc[mf][nf][0], acc[mf][nf][1]);
                if (i1 < N) *(float2*)&g_PQR[(size_t)i1 * 384 + col] = make_float2(acc[mf][nf][2], acc[mf][nf][3]);
            }
        }
        tt = ttn;
    }
}

// ---------------------------------------------------------------------------
// Kernel 2: edge kernel v9 = R12 structure + edge table + dynamic tickets.
// Tile = 64 edges, 256 threads, 3 CTAs/SM, 2 syncs/tile.
// ---------------------------------------------------------------------------
__global__ __launch_bounds__(256, 3) void edge_kernel(
    const float* __restrict__ W1, const float* __restrict__ b1,
    const float* __restrict__ b2, int N, int E)
{
    extern __shared__ unsigned sm[];
    unsigned* sT  = sm;              // 64*LDT words (bf16x2 t tile)
    float* sb1   = (float*)(sT + 64 * LDT);
    float* sb2   = sb1 + 128;
    float* swc   = sb2 + 128;
    __shared__ int sNext;
    int tid = threadIdx.x;

    if (tid < 128) { sb1[tid] = b1[tid]; sb2[tid] = b2[tid]; swc[tid] = W1[tid * 257 + 256]; }
    __syncthreads();

    int w = tid >> 5, l = tid & 31, g = l >> 2, t4 = l & 3;
    int wr = w & 1, wcc = w >> 1;     // 2 row-groups (32 rows) x 4 col-groups (32 cols)
    int ntiles = (E + 63) >> 6;

    int tt = blockIdx.x;
    while (tt < ntiles) {
        if (tid == 0) sNext = (int)atomicAdd(&g_tick_e, 1u);
        int e0 = tt << 6;

        // ---- build t tile (bf16x2): each warp covers edges w, w+8, ..., w+56 ----
        #pragma unroll
        for (int half = 0; half < 2; ++half) {
            float4 pv[4], qv[4]; float dv[4]; int el[4];
            #pragma unroll
            for (int it = 0; it < 4; ++it) {
                int e_loc = w + (half * 4 + it) * 8;
                el[it] = e_loc;
                int e = e0 + e_loc;
                uint4 ei = (e < E) ? g_edgeT[e] : make_uint4(0u, 0u, 0u, 0u);
                int s = (int)ei.x, r = (int)ei.y;
                dv[it] = __uint_as_float(ei.z);
                pv[it] = *(const float4*)&g_PQR[(size_t)s * 384 + l * 4];
                qv[it] = *(const float4*)&g_PQR[(size_t)r * 384 + 128 + l * 4];
            }
            #pragma unroll
            for (int it = 0; it < 4; ++it) {
                int c = l * 4;
                float x0 = pv[it].x + qv[it].x + dv[it] * swc[c + 0] + sb1[c + 0];
                float x1 = pv[it].y + qv[it].y + dv[it] * swc[c + 1] + sb1[c + 1];
                float x2 = pv[it].z + qv[it].z + dv[it] * swc[c + 2] + sb1[c + 2];
                float x3 = pv[it].w + qv[it].w + dv[it] * swc[c + 3] + sb1[c + 3];
                uint2 st = make_uint2(f2bf2(silu_fast(x0), silu_fast(x1)),
                                      f2bf2(silu_fast(x2), silu_fast(x3)));
                *(uint2*)&sT[el[it] * LDT + l * 2] = st;
            }
        }
        __syncthreads();           // sT built; sNext visible
        int ttn = sNext;

        // hoisted receiver-index load: latency hides under the mma loop
        int rowlane = wr * 32 + l;     // this warp's 32 tile-rows
        int e_r = e0 + rowlane;
        int vrec = (e_r < E) ? (int)g_edgeT[e_r].y : 0;

        // ---- GEMM2 (bf16): warp computes 32 rows (wr) x 32 cols (wcc) ----
        float acc[2][4][4];
        #pragma unroll
        for (int mf = 0; mf < 2; mf++)
            #pragma unroll
            for (int nf = 0; nf < 4; nf++)
                #pragma unroll
                for (int q = 0; q < 4; q++) acc[mf][nf][q] = 0.f;

        #pragma unroll
        for (int ks = 0; ks < 8; ++ks) {
            int kw = ks * 8;            // 8 bf16x2 words = 16 k-cols per step
            unsigned a[2][4];
            #pragma unroll
            for (int mf = 0; mf < 2; mf++) {
                int r0 = wr * 32 + mf * 16 + g;
                a[mf][0] = sT[r0 * LDT + kw + t4];
                a[mf][1] = sT[(r0 + 8) * LDT + kw + t4];
                a[mf][2] = sT[r0 * LDT + kw + t4 + 4];
                a[mf][3] = sT[(r0 + 8) * LDT + kw + t4 + 4];
            }
            uint4 q0 = g_W2pack[((ks * 4 + wcc) * 2 + 0) * 32 + l];
            uint4 q1 = g_W2pack[((ks * 4 + wcc) * 2 + 1) * 32 + l];
            unsigned bb[8] = { q0.x, q0.y, q0.z, q0.w, q1.x, q1.y, q1.z, q1.w };
            #pragma unroll
            for (int nf = 0; nf < 4; nf++) {
                mma16(acc[0][nf], a[0], &bb[nf * 2]);
                mma16(acc[1][nf], a[1], &bb[nf * 2]);
            }
        }
        __syncthreads();   // sT free for next tile's t-build

        // ---- scatter direct from regs: bias + silu, shfl-pair -> red.v4 ----
        #pragma unroll
        for (int mf = 0; mf < 2; mf++) {
            #pragma unroll
            for (int hh = 0; hh < 2; ++hh) {
                int rsel = mf * 16 + hh * 8 + g;
                int rec = __shfl_sync(0xffffffffu, vrec, rsel);
                bool valid = (e0 + wr * 32 + rsel) < E;
                #pragma unroll
                for (int nf = 0; nf < 4; nf++) {
                    int col = wcc * 32 + nf * 8 + t4 * 2;
                    float m0 = silu_fast(acc[mf][nf][hh * 2]     + sb2[col]);
                    float m1 = silu_fast(acc[mf][nf][hh * 2 + 1] + sb2[col + 1]);
                    // lane t4^1 holds the adjacent column pair
                    float n0 = __shfl_xor_sync(0xffffffffu, m0, 1);
                    float n1 = __shfl_xor_sync(0xffffffffu, m1, 1);
                    if (((t4 & 1) == 0) && valid) {
                        int cb = wcc * 32 + nf * 8 + (t4 >> 1) * 4;  // t4=0 -> +0, t4=2 -> +4
                        red4(&g_agg[(size_t)rec * D + cb], m0, m1, n0, n1);
                    }
                }
            }
        }
        tt = ttn;
    }
}

// ---------------------------------------------------------------------------
// Kernel 3: node update v2. 512 threads, tile 128 nodes, 2 CTAs/SM.
// Weights from L2-resident g_Upack; tf32 + exact silu.
// ---------------------------------------------------------------------------
__global__ __launch_bounds__(512, 2) void node_kernel(
    const float* __restrict__ h, const float* __restrict__ c1,
    const float* __restrict__ c2, float* __restrict__ out, int N)
{
    extern __shared__ unsigned sm[];
    unsigned* sA = sm;               // 128*LDA (agg tile, then t tile)
    float* sc1 = (float*)(sA + 128 * LDA);
    float* sc2 = sc1 + 128;
    int tid = threadIdx.x;

    if (tid < 128) { sc1[tid] = c1[tid]; sc2[tid] = c2[tid]; }

    int w = tid >> 5, l = tid & 31, g = l >> 2, t4 = l & 3;
    int wr = w >> 1, wc = w & 1;
    int ntiles = (N + 127) >> 7;

    for (int tt = blockIdx.x; tt < ntiles; tt += gridDim.x) {
        __syncthreads();
        int n0 = tt << 7;
        #pragma unroll
        for (int it = 0; it < 8; ++it) {
            int idx = tid + it * 512;
            int r = idx >> 5, q = idx & 31;
            int i = n0 + r;
            float4 v = make_float4(0.f, 0.f, 0.f, 0.f);
            if (i < N) v = *(const float4*)&g_agg[(size_t)i * D + q * 4];
            uint4 u = make_uint4(f2tf(v.x), f2tf(v.y), f2tf(v.z), f2tf(v.w));
            *(uint4*)&sA[r * LDA + q * 4] = u;
        }
        __syncthreads();

        float acc[8][4];
        #pragma unroll
        for (int nf = 0; nf < 8; nf++)
            #pragma unroll
            for (int q = 0; q < 4; q++) acc[nf][q] = 0.f;

        #pragma unroll
        for (int ks = 0; ks < 16; ++ks) {
            int kb = ks * 8;
            unsigned a[4];
            int r0 = wr * 16 + g;
            a[0] = sA[r0 * LDA + kb + t4];
            a[1] = sA[(r0 + 8) * LDA + kb + t4];
            a[2] = sA[r0 * LDA + kb + t4 + 4];
            a[3] = sA[(r0 + 8) * LDA + kb + t4 + 4];
            const uint4* up = &g_Upack[(((0 * 16 + ks) * 2 + wc) * 4) * 32 + l];
            uint4 q0 = up[0], q1 = up[32], q2 = up[64], q3 = up[96];
            unsigned bb[16] = { q0.x,q0.y,q0.z,q0.w, q1.x,q1.y,q1.z,q1.w,
                                q2.x,q2.y,q2.z,q2.w, q3.x,q3.y,q3.z,q3.w };
            #pragma unroll
            for (int nf = 0; nf < 8; nf++)
                mma8(acc[nf], a, &bb[nf * 2]);
        }
        __syncthreads();  // all warps done reading agg tile before overwrite with t

        int rA = wr * 16 + g;
        int i0 = n0 + rA, i1 = i0 + 8;
        #pragma unroll
        for (int nf = 0; nf < 8; nf++) {
            int col = wc * 64 + nf * 8 + t4 * 2;
            float r00 = 0.f, r01 = 0.f, r10 = 0.f, r11 = 0.f;
            if (i0 < N) { float2 rv = *(const float2*)&g_PQR[(size_t)i0 * 384 + 256 + col]; r00 = rv.x; r01 = rv.y; }
            if (i1 < N) { float2 rv = *(const float2*)&g_PQR[(size_t)i1 * 384 + 256 + col]; r10 = rv.x; r11 = rv.y; }
            sA[rA * LDA + col]           = f2tf(silu(acc[nf][0] + r00 + sc1[col]));
            sA[rA * LDA + col + 1]       = f2tf(silu(acc[nf][1] + r01 + sc1[col + 1]));
            sA[(rA + 8) * LDA + col]     = f2tf(silu(acc[nf][2] + r10 + sc1[col]));
            sA[(rA + 8) * LDA + col + 1] = f2tf(silu(acc[nf][3] + r11 + sc1[col + 1]));
        }
        __syncthreads();

        float acc2[8][4];
        #pragma unroll
        for (int nf = 0; nf < 8; nf++)
            #pragma unroll
            for (int q = 0; q < 4; q++) acc2[nf][q] = 0.f;

        #pragma unroll
        for (int ks = 0; ks < 16; ++ks) {
            int kb = ks * 8;
            unsigned a[4];
            int r0 = wr * 16 + g;
            a[0] = sA[r0 * LDA + kb + t4];
            a[1] = sA[(r0 + 8) * LDA + kb + t4];
            a[2] = sA[r0 * LDA + kb + t4 + 4];
            a[3] = sA[(r0 + 8) * LDA + kb + t4 + 4];
            const uint4* up = &g_Upack[(((1 * 16 + ks) * 2 + wc) * 4) * 32 + l];
            uint4 q0 = up[0], q1 = up[32], q2 = up[64], q3 = up[96];
            unsigned bb[16] = { q0.x,q0.y,q0.z,q0.w, q1.x,q1.y,q1.z,q1.w,
                                q2.x,q2.y,q2.z,q2.w, q3.x,q3.y,q3.z,q3.w };
            #pragma unroll
            for (int nf = 0; nf < 8; nf++)
                mma8(acc2[nf], a, &bb[nf * 2]);
        }

        #pragma unroll
        for (int nf = 0; nf < 8; nf++) {
            int col = wc * 64 + nf * 8 + t4 * 2;
            if (i0 < N) {
                float2 hv = *(const float2*)&h[(size_t)i0 * D + col];
                *(float2*)&out[(size_t)i0 * D + col] =
                    make_float2(hv.x + acc2[nf][0] + sc2[col], hv.y + acc2[nf][1] + sc2[col + 1]);
            }
            if (i1 < N) {
                float2 hv = *(const float2*)&h[(size_t)i1 * D + col];
                *(float2*)&out[(size_t)i1 * D + col] =
                    make_float2(hv.x + acc2[nf][2] + sc2[col], hv.y + acc2[nf][3] + sc2[col + 1]);
            }
        }
    }
}

// ---------------------------------------------------------------------------
extern "C" void kernel_launch(void* const* d_in, const int* in_sizes, int n_in,
                              void* d_out, int out_size)
{
    const float* h      = (const float*)d_in[0];
    const float* coords = (const float*)d_in[1];
    const void*  eraw   = (const void*)d_in[2];
    const float* W1     = (const float*)d_in[3];
    const float* b1     = (const float*)d_in[4];
    const float* W2     = (const float*)d_in[5];
    const float* b2     = (const float*)d_in[6];
    const float* U1     = (const float*)d_in[7];
    const float* c1     = (const float*)d_in[8];
    const float* U2     = (const float*)d_in[9];
    const float* c2     = (const float*)d_in[10];

    int N = in_sizes[0] / D;
    int E = in_sizes[2] / 2;
    if (N > MAXN) N = MAXN;
    if (E > MAXE) E = MAXE;

    const int SMEM1 = 32 * LDA * 4;                 // 16,896
    const int SMEM2 = 64 * LDT * 4 + 3 * 128 * 4;   // 18,944
    const int SMEM3 = 128 * LDA * 4 + 2 * 128 * 4;  // 68,608

    cudaFuncSetAttribute(gemm1_kernel, cudaFuncAttributeMaxDynamicSharedMemorySize, SMEM1);
    cudaFuncSetAttribute(edge_kernel,  cudaFuncAttributeMaxDynamicSharedMemorySize, SMEM2);
    cudaFuncSetAttribute(node_kernel,  cudaFuncAttributeMaxDynamicSharedMemorySize, SMEM3);

    void* aggPtr = nullptr;
    cudaGetSymbolAddress(&aggPtr, g_agg);
    cudaMemsetAsync(aggPtr, 0, (size_t)N * D * sizeof(float));
    void* flagPtr = nullptr;
    cudaGetSymbolAddress(&flagPtr, g_oddor);
    cudaMemsetAsync(flagPtr, 0, sizeof(int));

    probe_kernel<<<1, 256>>>((const int*)eraw);
    prep_edge_kernel<<<(E + 255) / 256, 256>>>(coords, eraw, N, E);
    pack_kernel<<<32, 256>>>(W2);
    pack_node_kernel<<<128, 256>>>(U1, U2);
    pack_gemm1_kernel<<<192, 256>>>(W1, U1);
    gemm1_kernel<<<GRIDG, 384, SMEM1>>>(h, N);
    edge_kernel<<<GRIDE, 256, SMEM2>>>(W1, b1, b2, N, E);
    node_kernel<<<304, 512, SMEM3>>>(h, c1, c2, (float*)d_out, N);
}